// round 6
// baseline (speedup 1.0000x reference)
#include <cuda_runtime.h>
#include <cuda_bf16.h>
#include <cstdint>
#include <math.h>

#define BSZ   8192
#define DDIM  1024
#define HDIM  1024
#define H2DIM 512
#define MMASK 15

typedef __nv_bfloat16 bf16;

// ---------------------------------------------------------------------------
// Scratch (__device__ globals; no allocations allowed)
// ---------------------------------------------------------------------------
__device__ bf16  g_xb [BSZ * DDIM];
__device__ bf16  g_ab [BSZ * DDIM];
__device__ bf16  g_wvt[DDIM * DDIM];            // Wv^T  [c, j]
__device__ bf16  g_wob[DDIM * DDIM];            // Wo    [n, j]
__device__ bf16  g_wcb[DDIM * DDIM];            // Wc = Wo@Wv  [n, k]
__device__ bf16  g_w1b[MMASK * HDIM * DDIM];    // W1^T per m: [H, D]
__device__ bf16  g_w2b[MMASK * H2DIM * HDIM];   // W2^T per m: [H2, H]
__device__ bf16  g_w3b[MMASK * DDIM * H2DIM];   // W3^T per m: [D, H2]
__device__ bf16  g_h1b[MMASK * BSZ * HDIM];
__device__ bf16  g_h2b[MMASK * BSZ * H2DIM];
__device__ float g_bc [DDIM];
__device__ float g_zeros[DDIM];                 // stays zero (zero-initialized)

// ---------------------------------------------------------------------------
// helpers
// ---------------------------------------------------------------------------
__device__ __forceinline__ uint32_t smem_u32(const void* p) {
    uint32_t a;
    asm("{ .reg .u64 t; cvta.to.shared.u64 t, %1; cvt.u32.u64 %0, t; }"
        : "=r"(a) : "l"(p));
    return a;
}

#define CP16(saddr, gptr) \
    asm volatile("cp.async.cg.shared.global [%0], [%1], 16;" \
                 :: "r"(saddr), "l"(gptr) : "memory")
#define CP_COMMIT() asm volatile("cp.async.commit_group;" ::: "memory")
#define CP_WAIT(n)  asm volatile("cp.async.wait_group %0;" :: "n"(n) : "memory")

#define LDSM4(r0, r1, r2, r3, addr) \
    asm volatile("ldmatrix.sync.aligned.m8n8.x4.shared.b16 {%0,%1,%2,%3}, [%4];" \
                 : "=r"(r0), "=r"(r1), "=r"(r2), "=r"(r3) : "r"(addr))

// D += A(16x16) * B(16x8), bf16 inputs, f32 accum
#define MMA_BF16(d, a, b0, b1) \
    asm volatile("mma.sync.aligned.m16n8k16.row.col.f32.bf16.bf16.f32 " \
        "{%0,%1,%2,%3}, {%4,%5,%6,%7}, {%8,%9}, {%0,%1,%2,%3};" \
        : "+f"((d)[0]), "+f"((d)[1]), "+f"((d)[2]), "+f"((d)[3]) \
        : "r"((a)[0]), "r"((a)[1]), "r"((a)[2]), "r"((a)[3]), "r"(b0), "r"(b1))

template <int ACT>
__device__ __forceinline__ float act_f(float v) {
    if (ACT == 1) return 0.5f * v * (1.0f + erff(v * 0.70710678118654752f));
    if (ACT == 2) return 1.0f / (1.0f + expf(-v));
    return v;
}

// ---------------------------------------------------------------------------
// bf16 tensor-core GEMM:  C[z] = act( A[z] @ B[z]^T + bias[z] )
//   A: [M,K] bf16 row-major.  B: [N,K] bf16 row-major.  bias: f32 [N].
//   OUTBF=1 -> C bf16, else f32.  ACT: 0 none, 1 exact GELU, 2 sigmoid.
// CTA 128x128, BK=64, 128 threads = 4 warps (2x2), warp tile 64x64.
// 3-stage cp.async ring, ONE __syncthreads per chunk; fragment loads are
// R4-style just-in-time LDSM (single-buffered -- known good).
// Requires M%128==0, N%128==0, K%64==0.
// ---------------------------------------------------------------------------
template <int ACT, int OUTBF>
__global__ void __launch_bounds__(128, 2) gemm_bf16(
    const bf16* __restrict__ A, const bf16* __restrict__ Bw,
    const float* __restrict__ bias, void* __restrict__ Cv,
    int N_, int K_, long sA, long sB, long sBias, long sC)
{
    constexpr int STR   = 72;          // halves; 144B row stride (9x16B, conflict-free)
    constexpr int TILE  = 128 * STR;   // halves per (A or B) tile
    constexpr int STAGE = 2 * TILE;    // halves per stage (A + B)

    extern __shared__ __align__(16) bf16 smem[];   // [3][2][TILE]
    const uint32_t sBase = smem_u32(smem);

    const int tid  = threadIdx.x;
    const int lane = tid & 31;
    const int wid  = tid >> 5;
    const int lr = lane >> 2, lc = lane & 3;
    const int wm = wid >> 1, wn = wid & 1;

    const int z  = blockIdx.z;
    const int n0 = blockIdx.x * 128;
    const long m0 = (long)blockIdx.y * 128;
    const bf16* Ap = A + (long)z * sA + m0 * K_;
    const bf16* Bp = Bw + (long)z * sB + (long)n0 * K_;
    const float* bp = bias + (long)z * sBias + n0;

    // ldmatrix per-thread base offsets (bytes) within a tile
    const uint32_t aOff = (uint32_t)(((wm * 64 + (lane & 15)) * STR + (lane >> 4) * 8) * 2);
    const uint32_t bOff = (uint32_t)(((wn * 64 + ((lane >> 4) * 8 + (lane & 7))) * STR
                                      + ((lane >> 3) & 1) * 8) * 2);

    float acc[4][8][4];
#pragma unroll
    for (int i = 0; i < 4; i++)
#pragma unroll
        for (int j = 0; j < 8; j++)
#pragma unroll
            for (int r = 0; r < 4; r++) acc[i][j][r] = 0.f;

    const int nchunks = K_ >> 6;

    auto load_tiles = [&](int k0, int stage) {
        const uint32_t sA0 = sBase + (uint32_t)(stage * STAGE * 2);
        const uint32_t sB0 = sA0 + (uint32_t)(TILE * 2);
#pragma unroll
        for (int j = 0; j < 8; j++) {
            int idx = tid + j * 128;
            int r = idx >> 3, c = (idx & 7) << 3;           // halves
            CP16(sA0 + (uint32_t)((r * STR + c) * 2), Ap + (long)r * K_ + k0 + c);
        }
#pragma unroll
        for (int j = 0; j < 8; j++) {
            int idx = tid + j * 128;
            int r = idx >> 3, c = (idx & 7) << 3;
            CP16(sB0 + (uint32_t)((r * STR + c) * 2), Bp + (long)r * K_ + k0 + c);
        }
    };

    // prologue: stages 0 and 1 (one commit group per chunk)
    load_tiles(0, 0);
    CP_COMMIT();
    if (nchunks > 1) {
        load_tiles(64, 1);
        CP_COMMIT();
    }

    int stage = 0;
    for (int ch = 0; ch < nchunks; ch++) {
        // chunk ch's group must be complete; chunk ch+1's may stay in flight
        if (ch + 1 < nchunks) { CP_WAIT(1); } else { CP_WAIT(0); }
        __syncthreads();   // ch data visible to all; all warps retired ch-1 reads

        // prefetch chunk ch+2 into stage (stage+2)%3 (that stage's readers done)
        if (ch + 2 < nchunks) {
            int st2 = stage + 2; if (st2 >= 3) st2 -= 3;
            load_tiles((ch + 2) << 6, st2);
            CP_COMMIT();
        }

        const uint32_t aBase = sBase + (uint32_t)(stage * STAGE * 2) + aOff;
        const uint32_t bBase = sBase + (uint32_t)(stage * STAGE * 2 + TILE * 2) + bOff;

#pragma unroll
        for (int ks = 0; ks < 4; ks++) {
            uint32_t ua[4][4], ub[4][4];
#pragma unroll
            for (int mi = 0; mi < 4; mi++)
                LDSM4(ua[mi][0], ua[mi][1], ua[mi][2], ua[mi][3],
                      aBase + (uint32_t)(mi * 16 * STR * 2 + ks * 32));
#pragma unroll
            for (int ni = 0; ni < 4; ni++)
                LDSM4(ub[ni][0], ub[ni][1], ub[ni][2], ub[ni][3],
                      bBase + (uint32_t)(ni * 16 * STR * 2 + ks * 32));
#pragma unroll
            for (int mi = 0; mi < 4; mi++)
#pragma unroll
                for (int ni = 0; ni < 4; ni++) {
                    MMA_BF16(acc[mi][2 * ni],     ua[mi], ub[ni][0], ub[ni][1]);
                    MMA_BF16(acc[mi][2 * ni + 1], ua[mi], ub[ni][2], ub[ni][3]);
                }
        }

        stage = stage + 1 == 3 ? 0 : stage + 1;
    }

    // ---- epilogue: bias + activation ----
#pragma unroll
    for (int mi = 0; mi < 4; mi++) {
        const long r0 = m0 + wm * 64 + mi * 16 + lr;
#pragma unroll
        for (int ni = 0; ni < 8; ni++) {
            const int col = wn * 64 + ni * 8 + 2 * lc;
            const float bi0 = bp[col], bi1 = bp[col + 1];
            float v0 = act_f<ACT>(acc[mi][ni][0] + bi0);
            float v1 = act_f<ACT>(acc[mi][ni][1] + bi1);
            float v2 = act_f<ACT>(acc[mi][ni][2] + bi0);
            float v3 = act_f<ACT>(acc[mi][ni][3] + bi1);
            if (OUTBF) {
                bf16* Cp = (bf16*)Cv + (long)z * sC;
                *(__nv_bfloat162*)(Cp + r0 * N_ + n0 + col) =
                    __floats2bfloat162_rn(v0, v1);
                *(__nv_bfloat162*)(Cp + (r0 + 8) * N_ + n0 + col) =
                    __floats2bfloat162_rn(v2, v3);
            } else {
                float* Cp = (float*)Cv + (long)z * sC;
                *(float2*)(Cp + r0 * N_ + n0 + col)       = make_float2(v0, v1);
                *(float2*)(Cp + (r0 + 8) * N_ + n0 + col) = make_float2(v2, v3);
            }
        }
    }
}

static constexpr int SMEM_SZ = 3 * 2 * 128 * 72 * 2;   // 110592 B

// ---------------------------------------------------------------------------
// fp32 -> bf16 flat convert (n multiple of 4)
// ---------------------------------------------------------------------------
__global__ __launch_bounds__(256) void conv_bf16(
    const float* __restrict__ s, bf16* __restrict__ d, long n4)
{
    long i = (long)blockIdx.x * blockDim.x + threadIdx.x;
    if (i < n4) {
        float4 v = ((const float4*)s)[i];
        ((__nv_bfloat162*)d)[2 * i]     = __floats2bfloat162_rn(v.x, v.y);
        ((__nv_bfloat162*)d)[2 * i + 1] = __floats2bfloat162_rn(v.z, v.w);
    }
}

// ---------------------------------------------------------------------------
// fp32 [R,C] -> bf16 [C,R] transpose-convert (R,C multiples of 32), z-batched
// ---------------------------------------------------------------------------
__global__ __launch_bounds__(256) void transp_bf16(
    const float* __restrict__ src, bf16* __restrict__ dst,
    int R, int C, long sS, long sD)
{
    __shared__ float t[32][33];
    const float* s = src + (long)blockIdx.z * sS;
    bf16* d = dst + (long)blockIdx.z * sD;
    const int c0 = blockIdx.x * 32, r0 = blockIdx.y * 32;
    const int tx = threadIdx.x & 31, ty = threadIdx.x >> 5;   // 32 x 8
#pragma unroll
    for (int k = 0; k < 4; k++)
        t[ty + 8 * k][tx] = s[(long)(r0 + ty + 8 * k) * C + c0 + tx];
    __syncthreads();
#pragma unroll
    for (int k = 0; k < 4; k++)
        d[(long)(c0 + ty + 8 * k) * R + r0 + tx] = __float2bfloat16(t[tx][ty + 8 * k]);
}

// ---------------------------------------------------------------------------
// bc[n] = Wo[n,:] . bv + bo[n]
// ---------------------------------------------------------------------------
__global__ __launch_bounds__(256) void bc_k(
    const float* __restrict__ Wo, const float* __restrict__ bv,
    const float* __restrict__ bo, float* __restrict__ bc)
{
    const int n = blockIdx.x, tid = threadIdx.x;
    float s = 0.f;
    for (int j = tid; j < DDIM; j += 256) s += Wo[(long)n * DDIM + j] * bv[j];
#pragma unroll
    for (int o = 16; o > 0; o >>= 1) s += __shfl_xor_sync(0xffffffffu, s, o);
    __shared__ float r[8];
    if ((tid & 31) == 0) r[tid >> 5] = s;
    __syncthreads();
    if (tid == 0) {
        float tot = 0.f;
#pragma unroll
        for (int i = 0; i < 8; i++) tot += r[i];
        bc[n] = tot + bo[n];
    }
}

// ---------------------------------------------------------------------------
// Per-row LayerNorm (H=1024) + exact GELU, in place on bf16 h[M*B, H].
// Stats in fp32.
// ---------------------------------------------------------------------------
__global__ __launch_bounds__(256) void ln_gelu_bf(
    bf16* __restrict__ h, const float* __restrict__ gamma,
    const float* __restrict__ beta)
{
    const long r = blockIdx.x;
    const int  m = (int)(r / BSZ);
    bf16* row = h + r * HDIM;
    const int tid = threadIdx.x;
    const int c0 = tid * 4;

    __nv_bfloat162 p0 = *(__nv_bfloat162*)(row + c0);
    __nv_bfloat162 p1 = *(__nv_bfloat162*)(row + c0 + 2);
    float x[4] = { __bfloat162float(p0.x), __bfloat162float(p0.y),
                   __bfloat162float(p1.x), __bfloat162float(p1.y) };

    __shared__ float red1[8];
    __shared__ float red2[8];

    float s = x[0] + x[1] + x[2] + x[3];
#pragma unroll
    for (int o = 16; o > 0; o >>= 1) s += __shfl_xor_sync(0xffffffffu, s, o);
    if ((tid & 31) == 0) red1[tid >> 5] = s;
    __syncthreads();
    float tot = 0.f;
#pragma unroll
    for (int i = 0; i < 8; i++) tot += red1[i];
    const float mu = tot * (1.0f / HDIM);

    float vs = 0.f;
#pragma unroll
    for (int i = 0; i < 4; i++) { float d = x[i] - mu; vs += d * d; }
#pragma unroll
    for (int o = 16; o > 0; o >>= 1) vs += __shfl_xor_sync(0xffffffffu, vs, o);
    if ((tid & 31) == 0) red2[tid >> 5] = vs;
    __syncthreads();
    float vtot = 0.f;
#pragma unroll
    for (int i = 0; i < 8; i++) vtot += red2[i];
    const float rstd = rsqrtf(vtot * (1.0f / HDIM) + 1e-5f);

    const float* gm = gamma + (long)m * HDIM + c0;
    const float* bm = beta  + (long)m * HDIM + c0;
    float y[4];
#pragma unroll
    for (int i = 0; i < 4; i++) {
        float t = (x[i] - mu) * rstd * gm[i] + bm[i];
        y[i] = 0.5f * t * (1.0f + erff(t * 0.70710678118654752f));
    }
    *(__nv_bfloat162*)(row + c0)     = __floats2bfloat162_rn(y[0], y[1]);
    *(__nv_bfloat162*)(row + c0 + 2) = __floats2bfloat162_rn(y[2], y[3]);
}

extern "C" void kernel_launch(void* const* d_in, const int* in_sizes, int n_in,
                              void* d_out, int out_size)
{
    const float* x     = (const float*)d_in[0];
    const float* in_w  = (const float*)d_in[1];   // [3D, D]
    const float* in_b  = (const float*)d_in[2];   // [3D]
    const float* out_w = (const float*)d_in[3];   // [D, D]
    const float* out_b = (const float*)d_in[4];   // [D]
    const float* W1    = (const float*)d_in[5];   // [M, D, H]
    const float* b1    = (const float*)d_in[6];   // [M, H]
    const float* ln_g  = (const float*)d_in[7];   // [M, H]
    const float* ln_b  = (const float*)d_in[8];   // [M, H]
    const float* W2    = (const float*)d_in[9];   // [M, H, H2]
    const float* b2    = (const float*)d_in[10];  // [M, H2]
    const float* W3    = (const float*)d_in[11];  // [M, H2, D]
    const float* b3    = (const float*)d_in[12];  // [M, D]
    float* out = (float*)d_out;                   // [M, B, D]

    bf16 *xb, *ab, *wvt, *wob, *wcb, *w1b, *w2b, *w3b, *h1b, *h2b;
    float *bc, *zeros;
    cudaGetSymbolAddress((void**)&xb,  g_xb);
    cudaGetSymbolAddress((void**)&ab,  g_ab);
    cudaGetSymbolAddress((void**)&wvt, g_wvt);
    cudaGetSymbolAddress((void**)&wob, g_wob);
    cudaGetSymbolAddress((void**)&wcb, g_wcb);
    cudaGetSymbolAddress((void**)&w1b, g_w1b);
    cudaGetSymbolAddress((void**)&w2b, g_w2b);
    cudaGetSymbolAddress((void**)&w3b, g_w3b);
    cudaGetSymbolAddress((void**)&h1b, g_h1b);
    cudaGetSymbolAddress((void**)&h2b, g_h2b);
    cudaGetSymbolAddress((void**)&bc,  g_bc);
    cudaGetSymbolAddress((void**)&zeros, g_zeros);

    cudaFuncSetAttribute(gemm_bf16<0, 1>, cudaFuncAttributeMaxDynamicSharedMemorySize, SMEM_SZ);
    cudaFuncSetAttribute(gemm_bf16<1, 1>, cudaFuncAttributeMaxDynamicSharedMemorySize, SMEM_SZ);
    cudaFuncSetAttribute(gemm_bf16<2, 0>, cudaFuncAttributeMaxDynamicSharedMemorySize, SMEM_SZ);

    // seq_len==1 => softmax over length-1 axis == 1 => attn == v.
    // a = x @ (Wo@Wv)^T + (Wo@bv + bo): fold both attention GEMMs into one.
    const float* Wv = in_w + (long)2 * DDIM * DDIM;
    const float* bv = in_b + 2 * DDIM;

    // --- prep: conversions ---
    conv_bf16<<<(BSZ * DDIM / 4 + 255) / 256, 256>>>(x, xb, BSZ * DDIM / 4);
    conv_bf16<<<(DDIM * DDIM / 4 + 255) / 256, 256>>>(out_w, wob, DDIM * DDIM / 4);
    transp_bf16<<<dim3(32, 32, 1), 256>>>(Wv, wvt, DDIM, DDIM, 0, 0);
    transp_bf16<<<dim3(32, 32, MMASK), 256>>>(W1, w1b, DDIM, HDIM,
        (long)DDIM * HDIM, (long)HDIM * DDIM);
    transp_bf16<<<dim3(16, 32, MMASK), 256>>>(W2, w2b, HDIM, H2DIM,
        (long)HDIM * H2DIM, (long)H2DIM * HDIM);
    transp_bf16<<<dim3(32, 16, MMASK), 256>>>(W3, w3b, H2DIM, DDIM,
        (long)H2DIM * DDIM, (long)DDIM * H2DIM);
    bc_k<<<DDIM, 256>>>(out_w, bv, out_b, bc);

    // Wc = Wo @ Wv  (bf16 out)
    gemm_bf16<0, 1><<<dim3(8, 8, 1), 128, SMEM_SZ>>>(
        wob, wvt, zeros, wcb, DDIM, DDIM, 0, 0, 0, 0);

    // a = x @ Wc^T + bc  (bf16 out)
    gemm_bf16<0, 1><<<dim3(8, 64, 1), 128, SMEM_SZ>>>(
        xb, wcb, bc, ab, DDIM, DDIM, 0, 0, 0, 0);

    // h1[m] = a @ W1[m] + b1[m]  (bf16 out)
    gemm_bf16<0, 1><<<dim3(8, 64, MMASK), 128, SMEM_SZ>>>(
        ab, w1b, b1, h1b, HDIM, DDIM,
        0, (long)HDIM * DDIM, (long)HDIM, (long)BSZ * HDIM);

    // LayerNorm + GELU in place (bf16)
    ln_gelu_bf<<<MMASK * BSZ, 256>>>(h1b, ln_g, ln_b);

    // h2[m] = gelu( h1[m] @ W2[m] + b2[m] )  (bf16 out)
    gemm_bf16<1, 1><<<dim3(4, 64, MMASK), 128, SMEM_SZ>>>(
        h1b, w2b, b2, h2b, H2DIM, HDIM,
        (long)BSZ * HDIM, (long)H2DIM * HDIM, (long)H2DIM, (long)BSZ * H2DIM);

    // out[m] = sigmoid( h2[m] @ W3[m] + b3[m] )  (f32 out)
    gemm_bf16<2, 0><<<dim3(8, 64, MMASK), 128, SMEM_SZ>>>(
        h2b, w3b, b3, out, DDIM, H2DIM,
        (long)BSZ * H2DIM, (long)DDIM * H2DIM, (long)DDIM, (long)BSZ * DDIM);
}

// round 7
// speedup vs baseline: 1.0575x; 1.0575x over previous
#include <cuda_runtime.h>
#include <cuda_bf16.h>
#include <cstdint>
#include <math.h>

#define BSZ   8192
#define DDIM  1024
#define HDIM  1024
#define H2DIM 512
#define MMASK 15

typedef __nv_bfloat16 bf16;

// ---------------------------------------------------------------------------
// Scratch (__device__ globals; no allocations allowed)
// ---------------------------------------------------------------------------
__device__ bf16  g_xb [BSZ * DDIM];
__device__ bf16  g_ab [BSZ * DDIM];
__device__ bf16  g_wvt[DDIM * DDIM];            // Wv^T  [c, j]
__device__ bf16  g_wob[DDIM * DDIM];            // Wo    [n, j]
__device__ bf16  g_wcb[DDIM * DDIM];            // Wc = Wo@Wv  [n, k]
__device__ bf16  g_w1b[MMASK * HDIM * DDIM];    // W1^T per m: [H, D]
__device__ bf16  g_w2b[MMASK * H2DIM * HDIM];   // W2^T per m: [H2, H]
__device__ bf16  g_w3b[MMASK * DDIM * H2DIM];   // W3^T per m: [D, H2]
__device__ bf16  g_h1b[MMASK * BSZ * HDIM];
__device__ bf16  g_h2b[MMASK * BSZ * H2DIM];
__device__ float g_bc [DDIM];
__device__ float g_zeros[DDIM];                 // stays zero (zero-initialized)

// ---------------------------------------------------------------------------
// helpers
// ---------------------------------------------------------------------------
__device__ __forceinline__ uint32_t smem_u32(const void* p) {
    uint32_t a;
    asm("{ .reg .u64 t; cvta.to.shared.u64 t, %1; cvt.u32.u64 %0, t; }"
        : "=r"(a) : "l"(p));
    return a;
}

#define CP16(saddr, gptr) \
    asm volatile("cp.async.cg.shared.global [%0], [%1], 16;" \
                 :: "r"(saddr), "l"(gptr) : "memory")
#define CP_COMMIT() asm volatile("cp.async.commit_group;" ::: "memory")
#define CP_WAIT(n)  asm volatile("cp.async.wait_group %0;" :: "n"(n) : "memory")

#define LDSM4(r0, r1, r2, r3, addr) \
    asm volatile("ldmatrix.sync.aligned.m8n8.x4.shared.b16 {%0,%1,%2,%3}, [%4];" \
                 : "=r"(r0), "=r"(r1), "=r"(r2), "=r"(r3) : "r"(addr))

// D += A(16x16) * B(16x8), bf16 inputs, f32 accum
#define MMA_BF16(d, a, b0, b1) \
    asm volatile("mma.sync.aligned.m16n8k16.row.col.f32.bf16.bf16.f32 " \
        "{%0,%1,%2,%3}, {%4,%5,%6,%7}, {%8,%9}, {%0,%1,%2,%3};" \
        : "+f"((d)[0]), "+f"((d)[1]), "+f"((d)[2]), "+f"((d)[3]) \
        : "r"((a)[0]), "r"((a)[1]), "r"((a)[2]), "r"((a)[3]), "r"(b0), "r"(b1))

template <int ACT>
__device__ __forceinline__ float act_f(float v) {
    if (ACT == 1) return 0.5f * v * (1.0f + erff(v * 0.70710678118654752f));
    if (ACT == 2) return 1.0f / (1.0f + expf(-v));
    return v;
}

// ---------------------------------------------------------------------------
// bf16 tensor-core GEMM:  C[z] = act( A[z] @ B[z]^T + bias[z] )
//   A: [M,K] bf16 row-major.  B: [N,K] bf16 row-major.  bias: f32 [N].
//   OUTBF=1 -> C bf16, else f32.  ACT: 0 none, 1 exact GELU, 2 sigmoid.
// CTA 128x128, BK=64, 128 threads = 4 warps (2x2), warp tile 64x64.
// 2-stage double-buffered cp.async (R4 core: 73.7KB smem keeps 84KB of L1D;
// the 3-stage/110KB variant starved L1 to 7KB and regressed).
// Requires M%128==0, N%128==0, K%64==0.
// ---------------------------------------------------------------------------
template <int ACT, int OUTBF>
__global__ void __launch_bounds__(128, 2) gemm_bf16(
    const bf16* __restrict__ A, const bf16* __restrict__ Bw,
    const float* __restrict__ bias, void* __restrict__ Cv,
    int N_, int K_, long sA, long sB, long sBias, long sC)
{
    constexpr int STR  = 72;          // halves; 144B row stride (9x16B, conflict-free)
    constexpr int ABUF = 128 * STR;   // halves per buffer

    extern __shared__ __align__(16) bf16 smem[];
    bf16* As = smem;                  // [2][128][STR]
    bf16* Bs = smem + 2 * ABUF;       // [2][128][STR]
    const uint32_t sAs = smem_u32(As);
    const uint32_t sBs = smem_u32(Bs);

    const int tid  = threadIdx.x;
    const int lane = tid & 31;
    const int wid  = tid >> 5;
    const int lr = lane >> 2, lc = lane & 3;
    const int wm = wid >> 1, wn = wid & 1;

    const int z  = blockIdx.z;
    const int n0 = blockIdx.x * 128;
    const long m0 = (long)blockIdx.y * 128;
    const bf16* Ap = A + (long)z * sA + m0 * K_;
    const bf16* Bp = Bw + (long)z * sB + (long)n0 * K_;
    const float* bp = bias + (long)z * sBias + n0;

    // ldmatrix per-thread base offsets (bytes)
    const uint32_t aOff = (uint32_t)(((wm * 64 + (lane & 15)) * STR + (lane >> 4) * 8) * 2);
    const uint32_t bOff = (uint32_t)(((wn * 64 + ((lane >> 4) * 8 + (lane & 7))) * STR
                                      + ((lane >> 3) & 1) * 8) * 2);

    float acc[4][8][4];
#pragma unroll
    for (int i = 0; i < 4; i++)
#pragma unroll
        for (int j = 0; j < 8; j++)
#pragma unroll
            for (int r = 0; r < 4; r++) acc[i][j][r] = 0.f;

    const int nchunks = K_ >> 6;

    auto load_tiles = [&](int k0, int buf) {
#pragma unroll
        for (int j = 0; j < 8; j++) {
            int idx = tid + j * 128;
            int r = idx >> 3, c = (idx & 7) << 3;           // halves
            CP16(sAs + (uint32_t)((buf * ABUF + r * STR + c) * 2),
                 Ap + (long)r * K_ + k0 + c);
        }
#pragma unroll
        for (int j = 0; j < 8; j++) {
            int idx = tid + j * 128;
            int r = idx >> 3, c = (idx & 7) << 3;
            CP16(sBs + (uint32_t)((buf * ABUF + r * STR + c) * 2),
                 Bp + (long)r * K_ + k0 + c);
        }
    };

    load_tiles(0, 0);
    CP_COMMIT();

    for (int ch = 0; ch < nchunks; ch++) {
        if (ch + 1 < nchunks) {
            load_tiles((ch + 1) << 6, (ch + 1) & 1);
            CP_COMMIT();
            CP_WAIT(1);
        } else {
            CP_WAIT(0);
        }
        __syncthreads();

        const uint32_t aBase = sAs + (uint32_t)((ch & 1) * ABUF * 2) + aOff;
        const uint32_t bBase = sBs + (uint32_t)((ch & 1) * ABUF * 2) + bOff;

#pragma unroll
        for (int ks = 0; ks < 4; ks++) {
            uint32_t ua[4][4], ub[4][4];
#pragma unroll
            for (int mi = 0; mi < 4; mi++)
                LDSM4(ua[mi][0], ua[mi][1], ua[mi][2], ua[mi][3],
                      aBase + (uint32_t)(mi * 16 * STR * 2 + ks * 32));
#pragma unroll
            for (int ni = 0; ni < 4; ni++)
                LDSM4(ub[ni][0], ub[ni][1], ub[ni][2], ub[ni][3],
                      bBase + (uint32_t)(ni * 16 * STR * 2 + ks * 32));
#pragma unroll
            for (int mi = 0; mi < 4; mi++)
#pragma unroll
                for (int ni = 0; ni < 4; ni++) {
                    MMA_BF16(acc[mi][2 * ni],     ua[mi], ub[ni][0], ub[ni][1]);
                    MMA_BF16(acc[mi][2 * ni + 1], ua[mi], ub[ni][2], ub[ni][3]);
                }
        }
        __syncthreads();
    }

    // ---- epilogue: bias + activation ----
#pragma unroll
    for (int mi = 0; mi < 4; mi++) {
        const long r0 = m0 + wm * 64 + mi * 16 + lr;
#pragma unroll
        for (int ni = 0; ni < 8; ni++) {
            const int col = wn * 64 + ni * 8 + 2 * lc;
            const float bi0 = bp[col], bi1 = bp[col + 1];
            float v0 = act_f<ACT>(acc[mi][ni][0] + bi0);
            float v1 = act_f<ACT>(acc[mi][ni][1] + bi1);
            float v2 = act_f<ACT>(acc[mi][ni][2] + bi0);
            float v3 = act_f<ACT>(acc[mi][ni][3] + bi1);
            if (OUTBF) {
                bf16* Cp = (bf16*)Cv + (long)z * sC;
                *(__nv_bfloat162*)(Cp + r0 * N_ + n0 + col) =
                    __floats2bfloat162_rn(v0, v1);
                *(__nv_bfloat162*)(Cp + (r0 + 8) * N_ + n0 + col) =
                    __floats2bfloat162_rn(v2, v3);
            } else {
                float* Cp = (float*)Cv + (long)z * sC;
                *(float2*)(Cp + r0 * N_ + n0 + col)       = make_float2(v0, v1);
                *(float2*)(Cp + (r0 + 8) * N_ + n0 + col) = make_float2(v2, v3);
            }
        }
    }
}

static constexpr int SMEM_SZ = 4 * 128 * 72 * 2;   // 73728 B

// ---------------------------------------------------------------------------
// fp32 -> bf16 flat convert (n multiple of 4)
// ---------------------------------------------------------------------------
__global__ __launch_bounds__(256) void conv_bf16(
    const float* __restrict__ s, bf16* __restrict__ d, long n4)
{
    long i = (long)blockIdx.x * blockDim.x + threadIdx.x;
    if (i < n4) {
        float4 v = ((const float4*)s)[i];
        ((__nv_bfloat162*)d)[2 * i]     = __floats2bfloat162_rn(v.x, v.y);
        ((__nv_bfloat162*)d)[2 * i + 1] = __floats2bfloat162_rn(v.z, v.w);
    }
}

// ---------------------------------------------------------------------------
// fp32 [R,C] -> bf16 [C,R] transpose-convert (R,C multiples of 32), z-batched
// ---------------------------------------------------------------------------
__global__ __launch_bounds__(256) void transp_bf16(
    const float* __restrict__ src, bf16* __restrict__ dst,
    int R, int C, long sS, long sD)
{
    __shared__ float t[32][33];
    const float* s = src + (long)blockIdx.z * sS;
    bf16* d = dst + (long)blockIdx.z * sD;
    const int c0 = blockIdx.x * 32, r0 = blockIdx.y * 32;
    const int tx = threadIdx.x & 31, ty = threadIdx.x >> 5;   // 32 x 8
#pragma unroll
    for (int k = 0; k < 4; k++)
        t[ty + 8 * k][tx] = s[(long)(r0 + ty + 8 * k) * C + c0 + tx];
    __syncthreads();
#pragma unroll
    for (int k = 0; k < 4; k++)
        d[(long)(c0 + ty + 8 * k) * R + r0 + tx] = __float2bfloat16(t[tx][ty + 8 * k]);
}

// ---------------------------------------------------------------------------
// bc[n] = Wo[n,:] . bv + bo[n]
// ---------------------------------------------------------------------------
__global__ __launch_bounds__(256) void bc_k(
    const float* __restrict__ Wo, const float* __restrict__ bv,
    const float* __restrict__ bo, float* __restrict__ bc)
{
    const int n = blockIdx.x, tid = threadIdx.x;
    float s = 0.f;
    for (int j = tid; j < DDIM; j += 256) s += Wo[(long)n * DDIM + j] * bv[j];
#pragma unroll
    for (int o = 16; o > 0; o >>= 1) s += __shfl_xor_sync(0xffffffffu, s, o);
    __shared__ float r[8];
    if ((tid & 31) == 0) r[tid >> 5] = s;
    __syncthreads();
    if (tid == 0) {
        float tot = 0.f;
#pragma unroll
        for (int i = 0; i < 8; i++) tot += r[i];
        bc[n] = tot + bo[n];
    }
}

// ---------------------------------------------------------------------------
// Per-row LayerNorm (H=1024) + exact GELU, in place on bf16 h[M*B, H].
// Stats in fp32.
// ---------------------------------------------------------------------------
__global__ __launch_bounds__(256) void ln_gelu_bf(
    bf16* __restrict__ h, const float* __restrict__ gamma,
    const float* __restrict__ beta)
{
    const long r = blockIdx.x;
    const int  m = (int)(r / BSZ);
    bf16* row = h + r * HDIM;
    const int tid = threadIdx.x;
    const int c0 = tid * 4;

    __nv_bfloat162 p0 = *(__nv_bfloat162*)(row + c0);
    __nv_bfloat162 p1 = *(__nv_bfloat162*)(row + c0 + 2);
    float x[4] = { __bfloat162float(p0.x), __bfloat162float(p0.y),
                   __bfloat162float(p1.x), __bfloat162float(p1.y) };

    __shared__ float red1[8];
    __shared__ float red2[8];

    float s = x[0] + x[1] + x[2] + x[3];
#pragma unroll
    for (int o = 16; o > 0; o >>= 1) s += __shfl_xor_sync(0xffffffffu, s, o);
    if ((tid & 31) == 0) red1[tid >> 5] = s;
    __syncthreads();
    float tot = 0.f;
#pragma unroll
    for (int i = 0; i < 8; i++) tot += red1[i];
    const float mu = tot * (1.0f / HDIM);

    float vs = 0.f;
#pragma unroll
    for (int i = 0; i < 4; i++) { float d = x[i] - mu; vs += d * d; }
#pragma unroll
    for (int o = 16; o > 0; o >>= 1) vs += __shfl_xor_sync(0xffffffffu, vs, o);
    if ((tid & 31) == 0) red2[tid >> 5] = vs;
    __syncthreads();
    float vtot = 0.f;
#pragma unroll
    for (int i = 0; i < 8; i++) vtot += red2[i];
    const float rstd = rsqrtf(vtot * (1.0f / HDIM) + 1e-5f);

    const float* gm = gamma + (long)m * HDIM + c0;
    const float* bm = beta  + (long)m * HDIM + c0;
    float y[4];
#pragma unroll
    for (int i = 0; i < 4; i++) {
        float t = (x[i] - mu) * rstd * gm[i] + bm[i];
        y[i] = 0.5f * t * (1.0f + erff(t * 0.70710678118654752f));
    }
    *(__nv_bfloat162*)(row + c0)     = __floats2bfloat162_rn(y[0], y[1]);
    *(__nv_bfloat162*)(row + c0 + 2) = __floats2bfloat162_rn(y[2], y[3]);
}

extern "C" void kernel_launch(void* const* d_in, const int* in_sizes, int n_in,
                              void* d_out, int out_size)
{
    const float* x     = (const float*)d_in[0];
    const float* in_w  = (const float*)d_in[1];   // [3D, D]
    const float* in_b  = (const float*)d_in[2];   // [3D]
    const float* out_w = (const float*)d_in[3];   // [D, D]
    const float* out_b = (const float*)d_in[4];   // [D]
    const float* W1    = (const float*)d_in[5];   // [M, D, H]
    const float* b1    = (const float*)d_in[6];   // [M, H]
    const float* ln_g  = (const float*)d_in[7];   // [M, H]
    const float* ln_b  = (const float*)d_in[8];   // [M, H]
    const float* W2    = (const float*)d_in[9];   // [M, H, H2]
    const float* b2    = (const float*)d_in[10];  // [M, H2]
    const float* W3    = (const float*)d_in[11];  // [M, H2, D]
    const float* b3    = (const float*)d_in[12];  // [M, D]
    float* out = (float*)d_out;                   // [M, B, D]

    bf16 *xb, *ab, *wvt, *wob, *wcb, *w1b, *w2b, *w3b, *h1b, *h2b;
    float *bc, *zeros;
    cudaGetSymbolAddress((void**)&xb,  g_xb);
    cudaGetSymbolAddress((void**)&ab,  g_ab);
    cudaGetSymbolAddress((void**)&wvt, g_wvt);
    cudaGetSymbolAddress((void**)&wob, g_wob);
    cudaGetSymbolAddress((void**)&wcb, g_wcb);
    cudaGetSymbolAddress((void**)&w1b, g_w1b);
    cudaGetSymbolAddress((void**)&w2b, g_w2b);
    cudaGetSymbolAddress((void**)&w3b, g_w3b);
    cudaGetSymbolAddress((void**)&h1b, g_h1b);
    cudaGetSymbolAddress((void**)&h2b, g_h2b);
    cudaGetSymbolAddress((void**)&bc,  g_bc);
    cudaGetSymbolAddress((void**)&zeros, g_zeros);

    cudaFuncSetAttribute(gemm_bf16<0, 1>, cudaFuncAttributeMaxDynamicSharedMemorySize, SMEM_SZ);
    cudaFuncSetAttribute(gemm_bf16<1, 1>, cudaFuncAttributeMaxDynamicSharedMemorySize, SMEM_SZ);
    cudaFuncSetAttribute(gemm_bf16<2, 0>, cudaFuncAttributeMaxDynamicSharedMemorySize, SMEM_SZ);

    // seq_len==1 => softmax over length-1 axis == 1 => attn == v.
    // a = x @ (Wo@Wv)^T + (Wo@bv + bo): fold both attention GEMMs into one.
    const float* Wv = in_w + (long)2 * DDIM * DDIM;
    const float* bv = in_b + 2 * DDIM;

    // --- prep: conversions ---
    conv_bf16<<<(BSZ * DDIM / 4 + 255) / 256, 256>>>(x, xb, BSZ * DDIM / 4);
    conv_bf16<<<(DDIM * DDIM / 4 + 255) / 256, 256>>>(out_w, wob, DDIM * DDIM / 4);
    transp_bf16<<<dim3(32, 32, 1), 256>>>(Wv, wvt, DDIM, DDIM, 0, 0);
    transp_bf16<<<dim3(32, 32, MMASK), 256>>>(W1, w1b, DDIM, HDIM,
        (long)DDIM * HDIM, (long)HDIM * DDIM);
    transp_bf16<<<dim3(16, 32, MMASK), 256>>>(W2, w2b, HDIM, H2DIM,
        (long)HDIM * H2DIM, (long)H2DIM * HDIM);
    transp_bf16<<<dim3(32, 16, MMASK), 256>>>(W3, w3b, H2DIM, DDIM,
        (long)H2DIM * DDIM, (long)DDIM * H2DIM);
    bc_k<<<DDIM, 256>>>(out_w, bv, out_b, bc);

    // Wc = Wo @ Wv  (bf16 out)
    gemm_bf16<0, 1><<<dim3(8, 8, 1), 128, SMEM_SZ>>>(
        wob, wvt, zeros, wcb, DDIM, DDIM, 0, 0, 0, 0);

    // a = x @ Wc^T + bc  (bf16 out)
    gemm_bf16<0, 1><<<dim3(8, 64, 1), 128, SMEM_SZ>>>(
        xb, wcb, bc, ab, DDIM, DDIM, 0, 0, 0, 0);

    // h1[m] = a @ W1[m] + b1[m]  (bf16 out)
    gemm_bf16<0, 1><<<dim3(8, 64, MMASK), 128, SMEM_SZ>>>(
        ab, w1b, b1, h1b, HDIM, DDIM,
        0, (long)HDIM * DDIM, (long)HDIM, (long)BSZ * HDIM);

    // LayerNorm + GELU in place (bf16)
    ln_gelu_bf<<<MMASK * BSZ, 256>>>(h1b, ln_g, ln_b);

    // h2[m] = gelu( h1[m] @ W2[m] + b2[m] )  (bf16 out)
    gemm_bf16<1, 1><<<dim3(4, 64, MMASK), 128, SMEM_SZ>>>(
        h1b, w2b, b2, h2b, H2DIM, HDIM,
        (long)BSZ * HDIM, (long)H2DIM * HDIM, (long)H2DIM, (long)BSZ * H2DIM);

    // out[m] = sigmoid( h2[m] @ W3[m] + b3[m] )  (f32 out)
    gemm_bf16<2, 0><<<dim3(8, 64, MMASK), 128, SMEM_SZ>>>(
        h2b, w3b, b3, out, DDIM, H2DIM,
        (long)BSZ * H2DIM, (long)DDIM * H2DIM, (long)DDIM, (long)BSZ * DDIM);
}

// round 8
// speedup vs baseline: 1.0859x; 1.0269x over previous
#include <cuda_runtime.h>
#include <cuda_bf16.h>
#include <cstdint>
#include <math.h>

#define BSZ   8192
#define DDIM  1024
#define HDIM  1024
#define H2DIM 512
#define MMASK 15

typedef __nv_bfloat16 bf16;

// ---------------------------------------------------------------------------
// Scratch (__device__ globals; no allocations allowed)
// ---------------------------------------------------------------------------
__device__ bf16  g_xb [BSZ * DDIM];
__device__ bf16  g_ab [BSZ * DDIM];
__device__ bf16  g_wvt[DDIM * DDIM];            // Wv^T  [c, j]
__device__ bf16  g_wob[DDIM * DDIM];            // Wo    [n, j]
__device__ bf16  g_wcb[DDIM * DDIM];            // Wc = Wo@Wv  [n, k]
__device__ bf16  g_w1b[MMASK * HDIM * DDIM];    // W1^T per m: [H, D]
__device__ bf16  g_w2b[MMASK * H2DIM * HDIM];   // W2^T per m: [H2, H]
__device__ bf16  g_w3b[MMASK * DDIM * H2DIM];   // W3^T per m: [D, H2]
__device__ bf16  g_h1b[MMASK * BSZ * HDIM];
__device__ bf16  g_h2b[MMASK * BSZ * H2DIM];
__device__ float g_bc [DDIM];
__device__ float g_zeros[DDIM];                 // stays zero (zero-initialized)

// ---------------------------------------------------------------------------
// helpers
// ---------------------------------------------------------------------------
__device__ __forceinline__ uint32_t smem_u32(const void* p) {
    uint32_t a;
    asm("{ .reg .u64 t; cvta.to.shared.u64 t, %1; cvt.u32.u64 %0, t; }"
        : "=r"(a) : "l"(p));
    return a;
}

#define CP16(saddr, gptr) \
    asm volatile("cp.async.cg.shared.global [%0], [%1], 16;" \
                 :: "r"(saddr), "l"(gptr) : "memory")
#define CP_COMMIT() asm volatile("cp.async.commit_group;" ::: "memory")
#define CP_WAIT(n)  asm volatile("cp.async.wait_group %0;" :: "n"(n) : "memory")

#define LDSM4(r0, r1, r2, r3, addr) \
    asm volatile("ldmatrix.sync.aligned.m8n8.x4.shared.b16 {%0,%1,%2,%3}, [%4];" \
                 : "=r"(r0), "=r"(r1), "=r"(r2), "=r"(r3) : "r"(addr))

// D += A(16x16) * B(16x8), bf16 inputs, f32 accum
#define MMA_BF16(d, a, b0, b1) \
    asm volatile("mma.sync.aligned.m16n8k16.row.col.f32.bf16.bf16.f32 " \
        "{%0,%1,%2,%3}, {%4,%5,%6,%7}, {%8,%9}, {%0,%1,%2,%3};" \
        : "+f"((d)[0]), "+f"((d)[1]), "+f"((d)[2]), "+f"((d)[3]) \
        : "r"((a)[0]), "r"((a)[1]), "r"((a)[2]), "r"((a)[3]), "r"(b0), "r"(b1))

template <int ACT>
__device__ __forceinline__ float act_f(float v) {
    if (ACT == 1) return 0.5f * v * (1.0f + erff(v * 0.70710678118654752f));
    if (ACT == 2) return 1.0f / (1.0f + expf(-v));
    return v;
}

// ---------------------------------------------------------------------------
// bf16 tensor-core GEMM:  C[z] = act( A[z] @ B[z]^T + bias[z] )
//   A: [M,K] bf16 row-major.  B: [N,K] bf16 row-major.  bias: f32 [N].
//   OUTBF=1 -> C bf16, else f32.  ACT: 0 none, 1 exact GELU, 2 sigmoid.
// CTA 128x128, BK=64, 128 threads = 4 warps (2x2), warp tile 64x64.
// 2-stage cp.async, ONE __syncthreads per chunk (wait -> sync -> prefetch ->
// compute). 73.7KB smem keeps L1D healthy (the 110KB 3-stage variant starved
// L1 to 7KB and regressed). Main loop is MMA-issue-bound (~1 HMMA/4cyc/SM).
// Requires M%128==0, N%128==0, K%64==0.
// ---------------------------------------------------------------------------
template <int ACT, int OUTBF>
__global__ void __launch_bounds__(128, 2) gemm_bf16(
    const bf16* __restrict__ A, const bf16* __restrict__ Bw,
    const float* __restrict__ bias, void* __restrict__ Cv,
    int N_, int K_, long sA, long sB, long sBias, long sC)
{
    constexpr int STR  = 72;          // halves; 144B row stride (9x16B, conflict-free)
    constexpr int ABUF = 128 * STR;   // halves per buffer

    extern __shared__ __align__(16) bf16 smem[];
    bf16* As = smem;                  // [2][128][STR]
    bf16* Bs = smem + 2 * ABUF;       // [2][128][STR]
    const uint32_t sAs = smem_u32(As);
    const uint32_t sBs = smem_u32(Bs);

    const int tid  = threadIdx.x;
    const int lane = tid & 31;
    const int wid  = tid >> 5;
    const int lr = lane >> 2, lc = lane & 3;
    const int wm = wid >> 1, wn = wid & 1;

    const int z  = blockIdx.z;
    const int n0 = blockIdx.x * 128;
    const long m0 = (long)blockIdx.y * 128;
    const bf16* Ap = A + (long)z * sA + m0 * K_;
    const bf16* Bp = Bw + (long)z * sB + (long)n0 * K_;
    const float* bp = bias + (long)z * sBias + n0;

    // ldmatrix per-thread base offsets (bytes)
    const uint32_t aOff = (uint32_t)(((wm * 64 + (lane & 15)) * STR + (lane >> 4) * 8) * 2);
    const uint32_t bOff = (uint32_t)(((wn * 64 + ((lane >> 4) * 8 + (lane & 7))) * STR
                                      + ((lane >> 3) & 1) * 8) * 2);

    float acc[4][8][4];
#pragma unroll
    for (int i = 0; i < 4; i++)
#pragma unroll
        for (int j = 0; j < 8; j++)
#pragma unroll
            for (int r = 0; r < 4; r++) acc[i][j][r] = 0.f;

    const int nchunks = K_ >> 6;

    auto load_tiles = [&](int k0, int buf) {
#pragma unroll
        for (int j = 0; j < 8; j++) {
            int idx = tid + j * 128;
            int r = idx >> 3, c = (idx & 7) << 3;           // halves
            CP16(sAs + (uint32_t)((buf * ABUF + r * STR + c) * 2),
                 Ap + (long)r * K_ + k0 + c);
        }
#pragma unroll
        for (int j = 0; j < 8; j++) {
            int idx = tid + j * 128;
            int r = idx >> 3, c = (idx & 7) << 3;
            CP16(sBs + (uint32_t)((buf * ABUF + r * STR + c) * 2),
                 Bp + (long)r * K_ + k0 + c);
        }
    };

    load_tiles(0, 0);
    CP_COMMIT();

    for (int ch = 0; ch < nchunks; ch++) {
        CP_WAIT(0);        // chunk ch's group (issued last iteration) complete
        __syncthreads();   // data visible; all warps done reading buf (ch+1)&1

        if (ch + 1 < nchunks) {
            load_tiles((ch + 1) << 6, (ch + 1) & 1);
            CP_COMMIT();   // proceeds in background during compute below
        }

        const uint32_t aBase = sAs + (uint32_t)((ch & 1) * ABUF * 2) + aOff;
        const uint32_t bBase = sBs + (uint32_t)((ch & 1) * ABUF * 2) + bOff;

#pragma unroll
        for (int ks = 0; ks < 4; ks++) {
            uint32_t ua[4][4], ub[4][4];
#pragma unroll
            for (int mi = 0; mi < 4; mi++)
                LDSM4(ua[mi][0], ua[mi][1], ua[mi][2], ua[mi][3],
                      aBase + (uint32_t)(mi * 16 * STR * 2 + ks * 32));
#pragma unroll
            for (int ni = 0; ni < 4; ni++)
                LDSM4(ub[ni][0], ub[ni][1], ub[ni][2], ub[ni][3],
                      bBase + (uint32_t)(ni * 16 * STR * 2 + ks * 32));
#pragma unroll
            for (int mi = 0; mi < 4; mi++)
#pragma unroll
                for (int ni = 0; ni < 4; ni++) {
                    MMA_BF16(acc[mi][2 * ni],     ua[mi], ub[ni][0], ub[ni][1]);
                    MMA_BF16(acc[mi][2 * ni + 1], ua[mi], ub[ni][2], ub[ni][3]);
                }
        }
    }

    // ---- epilogue: bias + activation ----
#pragma unroll
    for (int mi = 0; mi < 4; mi++) {
        const long r0 = m0 + wm * 64 + mi * 16 + lr;
#pragma unroll
        for (int ni = 0; ni < 8; ni++) {
            const int col = wn * 64 + ni * 8 + 2 * lc;
            const float bi0 = bp[col], bi1 = bp[col + 1];
            float v0 = act_f<ACT>(acc[mi][ni][0] + bi0);
            float v1 = act_f<ACT>(acc[mi][ni][1] + bi1);
            float v2 = act_f<ACT>(acc[mi][ni][2] + bi0);
            float v3 = act_f<ACT>(acc[mi][ni][3] + bi1);
            if (OUTBF) {
                bf16* Cp = (bf16*)Cv + (long)z * sC;
                *(__nv_bfloat162*)(Cp + r0 * N_ + n0 + col) =
                    __floats2bfloat162_rn(v0, v1);
                *(__nv_bfloat162*)(Cp + (r0 + 8) * N_ + n0 + col) =
                    __floats2bfloat162_rn(v2, v3);
            } else {
                float* Cp = (float*)Cv + (long)z * sC;
                *(float2*)(Cp + r0 * N_ + n0 + col)       = make_float2(v0, v1);
                *(float2*)(Cp + (r0 + 8) * N_ + n0 + col) = make_float2(v2, v3);
            }
        }
    }
}

static constexpr int SMEM_SZ = 4 * 128 * 72 * 2;   // 73728 B

// ---------------------------------------------------------------------------
// fp32 -> bf16 flat convert (n multiple of 4)
// ---------------------------------------------------------------------------
__global__ __launch_bounds__(256) void conv_bf16(
    const float* __restrict__ s, bf16* __restrict__ d, long n4)
{
    long i = (long)blockIdx.x * blockDim.x + threadIdx.x;
    if (i < n4) {
        float4 v = ((const float4*)s)[i];
        ((__nv_bfloat162*)d)[2 * i]     = __floats2bfloat162_rn(v.x, v.y);
        ((__nv_bfloat162*)d)[2 * i + 1] = __floats2bfloat162_rn(v.z, v.w);
    }
}

// ---------------------------------------------------------------------------
// fp32 [R,C] -> bf16 [C,R] transpose-convert (R,C multiples of 32), z-batched
// ---------------------------------------------------------------------------
__global__ __launch_bounds__(256) void transp_bf16(
    const float* __restrict__ src, bf16* __restrict__ dst,
    int R, int C, long sS, long sD)
{
    __shared__ float t[32][33];
    const float* s = src + (long)blockIdx.z * sS;
    bf16* d = dst + (long)blockIdx.z * sD;
    const int c0 = blockIdx.x * 32, r0 = blockIdx.y * 32;
    const int tx = threadIdx.x & 31, ty = threadIdx.x >> 5;   // 32 x 8
#pragma unroll
    for (int k = 0; k < 4; k++)
        t[ty + 8 * k][tx] = s[(long)(r0 + ty + 8 * k) * C + c0 + tx];
    __syncthreads();
#pragma unroll
    for (int k = 0; k < 4; k++)
        d[(long)(c0 + ty + 8 * k) * R + r0 + tx] = __float2bfloat16(t[tx][ty + 8 * k]);
}

// ---------------------------------------------------------------------------
// bc[n] = Wo[n,:] . bv + bo[n]
// ---------------------------------------------------------------------------
__global__ __launch_bounds__(256) void bc_k(
    const float* __restrict__ Wo, const float* __restrict__ bv,
    const float* __restrict__ bo, float* __restrict__ bc)
{
    const int n = blockIdx.x, tid = threadIdx.x;
    float s = 0.f;
    for (int j = tid; j < DDIM; j += 256) s += Wo[(long)n * DDIM + j] * bv[j];
#pragma unroll
    for (int o = 16; o > 0; o >>= 1) s += __shfl_xor_sync(0xffffffffu, s, o);
    __shared__ float r[8];
    if ((tid & 31) == 0) r[tid >> 5] = s;
    __syncthreads();
    if (tid == 0) {
        float tot = 0.f;
#pragma unroll
        for (int i = 0; i < 8; i++) tot += r[i];
        bc[n] = tot + bo[n];
    }
}

// ---------------------------------------------------------------------------
// Per-row LayerNorm (H=1024) + exact GELU, in place on bf16 h[M*B, H].
// 128 threads/row, 8 elems/thread, single-pass sum/sumsq, one sync.
// ---------------------------------------------------------------------------
__global__ __launch_bounds__(128) void ln_gelu_bf(
    bf16* __restrict__ h, const float* __restrict__ gamma,
    const float* __restrict__ beta)
{
    const long r = blockIdx.x;
    const int  m = (int)(r / BSZ);
    bf16* row = h + r * HDIM;
    const int tid = threadIdx.x;
    const int c0 = tid * 8;

    uint4 pk = *(const uint4*)(row + c0);
    float x[8];
    {
        __nv_bfloat162 q0 = *(__nv_bfloat162*)&pk.x;
        __nv_bfloat162 q1 = *(__nv_bfloat162*)&pk.y;
        __nv_bfloat162 q2 = *(__nv_bfloat162*)&pk.z;
        __nv_bfloat162 q3 = *(__nv_bfloat162*)&pk.w;
        x[0] = __bfloat162float(q0.x); x[1] = __bfloat162float(q0.y);
        x[2] = __bfloat162float(q1.x); x[3] = __bfloat162float(q1.y);
        x[4] = __bfloat162float(q2.x); x[5] = __bfloat162float(q2.y);
        x[6] = __bfloat162float(q3.x); x[7] = __bfloat162float(q3.y);
    }

    float s = 0.f, s2 = 0.f;
#pragma unroll
    for (int i = 0; i < 8; i++) { s += x[i]; s2 += x[i] * x[i]; }
#pragma unroll
    for (int o = 16; o > 0; o >>= 1) {
        s  += __shfl_xor_sync(0xffffffffu, s,  o);
        s2 += __shfl_xor_sync(0xffffffffu, s2, o);
    }
    __shared__ float sm1[4], sm2[4];
    if ((tid & 31) == 0) { sm1[tid >> 5] = s; sm2[tid >> 5] = s2; }
    __syncthreads();
    const float tot  = sm1[0] + sm1[1] + sm1[2] + sm1[3];
    const float tot2 = sm2[0] + sm2[1] + sm2[2] + sm2[3];
    const float mu   = tot * (1.0f / HDIM);
    const float var  = fmaxf(tot2 * (1.0f / HDIM) - mu * mu, 0.f);
    const float rstd = rsqrtf(var + 1e-5f);

    const float* gm = gamma + (long)m * HDIM + c0;
    const float* bm = beta  + (long)m * HDIM + c0;
    float4 g0 = *(const float4*)gm, g1 = *(const float4*)(gm + 4);
    float4 b0 = *(const float4*)bm, b1 = *(const float4*)(bm + 4);
    float g[8] = {g0.x, g0.y, g0.z, g0.w, g1.x, g1.y, g1.z, g1.w};
    float b[8] = {b0.x, b0.y, b0.z, b0.w, b1.x, b1.y, b1.z, b1.w};

    __nv_bfloat162 o2[4];
#pragma unroll
    for (int i = 0; i < 4; i++) {
        float t0 = (x[2 * i]     - mu) * rstd * g[2 * i]     + b[2 * i];
        float t1 = (x[2 * i + 1] - mu) * rstd * g[2 * i + 1] + b[2 * i + 1];
        t0 = 0.5f * t0 * (1.0f + erff(t0 * 0.70710678118654752f));
        t1 = 0.5f * t1 * (1.0f + erff(t1 * 0.70710678118654752f));
        o2[i] = __floats2bfloat162_rn(t0, t1);
    }
    *(uint4*)(row + c0) = *(uint4*)o2;
}

extern "C" void kernel_launch(void* const* d_in, const int* in_sizes, int n_in,
                              void* d_out, int out_size)
{
    const float* x     = (const float*)d_in[0];
    const float* in_w  = (const float*)d_in[1];   // [3D, D]
    const float* in_b  = (const float*)d_in[2];   // [3D]
    const float* out_w = (const float*)d_in[3];   // [D, D]
    const float* out_b = (const float*)d_in[4];   // [D]
    const float* W1    = (const float*)d_in[5];   // [M, D, H]
    const float* b1    = (const float*)d_in[6];   // [M, H]
    const float* ln_g  = (const float*)d_in[7];   // [M, H]
    const float* ln_b  = (const float*)d_in[8];   // [M, H]
    const float* W2    = (const float*)d_in[9];   // [M, H, H2]
    const float* b2    = (const float*)d_in[10];  // [M, H2]
    const float* W3    = (const float*)d_in[11];  // [M, H2, D]
    const float* b3    = (const float*)d_in[12];  // [M, D]
    float* out = (float*)d_out;                   // [M, B, D]

    bf16 *xb, *ab, *wvt, *wob, *wcb, *w1b, *w2b, *w3b, *h1b, *h2b;
    float *bc, *zeros;
    cudaGetSymbolAddress((void**)&xb,  g_xb);
    cudaGetSymbolAddress((void**)&ab,  g_ab);
    cudaGetSymbolAddress((void**)&wvt, g_wvt);
    cudaGetSymbolAddress((void**)&wob, g_wob);
    cudaGetSymbolAddress((void**)&wcb, g_wcb);
    cudaGetSymbolAddress((void**)&w1b, g_w1b);
    cudaGetSymbolAddress((void**)&w2b, g_w2b);
    cudaGetSymbolAddress((void**)&w3b, g_w3b);
    cudaGetSymbolAddress((void**)&h1b, g_h1b);
    cudaGetSymbolAddress((void**)&h2b, g_h2b);
    cudaGetSymbolAddress((void**)&bc,  g_bc);
    cudaGetSymbolAddress((void**)&zeros, g_zeros);

    cudaFuncSetAttribute(gemm_bf16<0, 1>, cudaFuncAttributeMaxDynamicSharedMemorySize, SMEM_SZ);
    cudaFuncSetAttribute(gemm_bf16<1, 1>, cudaFuncAttributeMaxDynamicSharedMemorySize, SMEM_SZ);
    cudaFuncSetAttribute(gemm_bf16<2, 0>, cudaFuncAttributeMaxDynamicSharedMemorySize, SMEM_SZ);

    // seq_len==1 => softmax over length-1 axis == 1 => attn == v.
    // a = x @ (Wo@Wv)^T + (Wo@bv + bo): fold both attention GEMMs into one.
    const float* Wv = in_w + (long)2 * DDIM * DDIM;
    const float* bv = in_b + 2 * DDIM;

    // --- prep: conversions ---
    conv_bf16<<<(BSZ * DDIM / 4 + 255) / 256, 256>>>(x, xb, BSZ * DDIM / 4);
    conv_bf16<<<(DDIM * DDIM / 4 + 255) / 256, 256>>>(out_w, wob, DDIM * DDIM / 4);
    transp_bf16<<<dim3(32, 32, 1), 256>>>(Wv, wvt, DDIM, DDIM, 0, 0);
    transp_bf16<<<dim3(32, 32, MMASK), 256>>>(W1, w1b, DDIM, HDIM,
        (long)DDIM * HDIM, (long)HDIM * DDIM);
    transp_bf16<<<dim3(16, 32, MMASK), 256>>>(W2, w2b, HDIM, H2DIM,
        (long)HDIM * H2DIM, (long)H2DIM * HDIM);
    transp_bf16<<<dim3(32, 16, MMASK), 256>>>(W3, w3b, H2DIM, DDIM,
        (long)H2DIM * DDIM, (long)DDIM * H2DIM);
    bc_k<<<DDIM, 256>>>(out_w, bv, out_b, bc);

    // Wc = Wo @ Wv  (bf16 out)
    gemm_bf16<0, 1><<<dim3(8, 8, 1), 128, SMEM_SZ>>>(
        wob, wvt, zeros, wcb, DDIM, DDIM, 0, 0, 0, 0);

    // a = x @ Wc^T + bc  (bf16 out)
    gemm_bf16<0, 1><<<dim3(8, 64, 1), 128, SMEM_SZ>>>(
        xb, wcb, bc, ab, DDIM, DDIM, 0, 0, 0, 0);

    // h1[m] = a @ W1[m] + b1[m]  (bf16 out)
    gemm_bf16<0, 1><<<dim3(8, 64, MMASK), 128, SMEM_SZ>>>(
        ab, w1b, b1, h1b, HDIM, DDIM,
        0, (long)HDIM * DDIM, (long)HDIM, (long)BSZ * HDIM);

    // LayerNorm + GELU in place (bf16)
    ln_gelu_bf<<<MMASK * BSZ, 128>>>(h1b, ln_g, ln_b);

    // h2[m] = gelu( h1[m] @ W2[m] + b2[m] )  (bf16 out)
    gemm_bf16<1, 1><<<dim3(4, 64, MMASK), 128, SMEM_SZ>>>(
        h1b, w2b, b2, h2b, H2DIM, HDIM,
        (long)BSZ * HDIM, (long)H2DIM * HDIM, (long)H2DIM, (long)BSZ * H2DIM);

    // out[m] = sigmoid( h2[m] @ W3[m] + b3[m] )  (f32 out)
    gemm_bf16<2, 0><<<dim3(8, 64, MMASK), 128, SMEM_SZ>>>(
        h2b, w3b, b3, out, DDIM, H2DIM,
        (long)BSZ * H2DIM, (long)DDIM * H2DIM, (long)DDIM, (long)BSZ * DDIM);
}

// round 9
// speedup vs baseline: 1.0870x; 1.0010x over previous
#include <cuda_runtime.h>
#include <cuda_bf16.h>
#include <cstdint>
#include <math.h>

#define BSZ   8192
#define DDIM  1024
#define HDIM  1024
#define H2DIM 512
#define MMASK 15

typedef __nv_bfloat16 bf16;

// ---------------------------------------------------------------------------
// Scratch (__device__ globals; no allocations allowed)
// ---------------------------------------------------------------------------
__device__ bf16  g_xb [BSZ * DDIM];
__device__ bf16  g_ab [BSZ * DDIM];
__device__ bf16  g_wvt[DDIM * DDIM];            // Wv^T  [c, j]
__device__ bf16  g_wob[DDIM * DDIM];            // Wo    [n, j]
__device__ bf16  g_wcb[DDIM * DDIM];            // Wc = Wo@Wv  [n, k]
__device__ bf16  g_w1b[MMASK * HDIM * DDIM];    // W1^T per m: [H, D]
__device__ bf16  g_w2b[MMASK * H2DIM * HDIM];   // W2^T per m: [H2, H]
__device__ bf16  g_w3b[MMASK * DDIM * H2DIM];   // W3^T per m: [D, H2]
__device__ bf16  g_h1b[MMASK * BSZ * HDIM];
__device__ bf16  g_h2b[MMASK * BSZ * H2DIM];
__device__ float g_bc [DDIM];
__device__ float g_zeros[DDIM];                 // stays zero (zero-initialized)

// ---------------------------------------------------------------------------
// helpers
// ---------------------------------------------------------------------------
__device__ __forceinline__ uint32_t smem_u32(const void* p) {
    uint32_t a;
    asm("{ .reg .u64 t; cvta.to.shared.u64 t, %1; cvt.u32.u64 %0, t; }"
        : "=r"(a) : "l"(p));
    return a;
}

#define CP16(saddr, gptr) \
    asm volatile("cp.async.cg.shared.global [%0], [%1], 16;" \
                 :: "r"(saddr), "l"(gptr) : "memory")
#define CP_COMMIT() asm volatile("cp.async.commit_group;" ::: "memory")
#define CP_WAIT(n)  asm volatile("cp.async.wait_group %0;" :: "n"(n) : "memory")

#define LDSM4(r0, r1, r2, r3, addr) \
    asm volatile("ldmatrix.sync.aligned.m8n8.x4.shared.b16 {%0,%1,%2,%3}, [%4];" \
                 : "=r"(r0), "=r"(r1), "=r"(r2), "=r"(r3) : "r"(addr))

// D += A(16x16) * B(16x8), bf16 inputs, f32 accum
#define MMA_BF16(d, a, b0, b1) \
    asm volatile("mma.sync.aligned.m16n8k16.row.col.f32.bf16.bf16.f32 " \
        "{%0,%1,%2,%3}, {%4,%5,%6,%7}, {%8,%9}, {%0,%1,%2,%3};" \
        : "+f"((d)[0]), "+f"((d)[1]), "+f"((d)[2]), "+f"((d)[3]) \
        : "r"((a)[0]), "r"((a)[1]), "r"((a)[2]), "r"((a)[3]), "r"(b0), "r"(b1))

template <int ACT>
__device__ __forceinline__ float act_f(float v) {
    if (ACT == 1) return 0.5f * v * (1.0f + erff(v * 0.70710678118654752f));
    if (ACT == 2) return 1.0f / (1.0f + expf(-v));
    return v;
}

// ---------------------------------------------------------------------------
// bf16 tensor-core GEMM:  C[z] = act( A[z] @ B[z]^T + bias[z] )
//   A: [M,K] bf16 row-major.  B: [N,K] bf16 row-major.  bias: f32 [N].
//   OUTBF=1 -> C bf16, else f32.  ACT: 0 none, 1 exact GELU, 2 sigmoid.
// CTA 128x128, BK=64, 128 threads = 4 warps (2x2), warp tile 64x64.
// 2-stage cp.async, ONE __syncthreads per chunk, PLUS register-level
// fragment double-buffering: LDSM for k-step ks+1 issued before the MMAs of
// ks, hiding LDS latency behind tensor issue. 73.7KB smem keeps L1D healthy.
// Requires M%128==0, N%128==0, K%64==0.
// ---------------------------------------------------------------------------
template <int ACT, int OUTBF>
__global__ void __launch_bounds__(128, 2) gemm_bf16(
    const bf16* __restrict__ A, const bf16* __restrict__ Bw,
    const float* __restrict__ bias, void* __restrict__ Cv,
    int N_, int K_, long sA, long sB, long sBias, long sC)
{
    constexpr int STR  = 72;          // halves; 144B row stride (9x16B, conflict-free)
    constexpr int ABUF = 128 * STR;   // halves per buffer

    extern __shared__ __align__(16) bf16 smem[];
    bf16* As = smem;                  // [2][128][STR]
    bf16* Bs = smem + 2 * ABUF;       // [2][128][STR]
    const uint32_t sAs = smem_u32(As);
    const uint32_t sBs = smem_u32(Bs);

    const int tid  = threadIdx.x;
    const int lane = tid & 31;
    const int wid  = tid >> 5;
    const int lr = lane >> 2, lc = lane & 3;
    const int wm = wid >> 1, wn = wid & 1;

    const int z  = blockIdx.z;
    const int n0 = blockIdx.x * 128;
    const long m0 = (long)blockIdx.y * 128;
    const bf16* Ap = A + (long)z * sA + m0 * K_;
    const bf16* Bp = Bw + (long)z * sB + (long)n0 * K_;
    const float* bp = bias + (long)z * sBias + n0;

    // ldmatrix per-thread base offsets (bytes)
    const uint32_t aOff = (uint32_t)(((wm * 64 + (lane & 15)) * STR + (lane >> 4) * 8) * 2);
    const uint32_t bOff = (uint32_t)(((wn * 64 + ((lane >> 4) * 8 + (lane & 7))) * STR
                                      + ((lane >> 3) & 1) * 8) * 2);

    float acc[4][8][4];
#pragma unroll
    for (int i = 0; i < 4; i++)
#pragma unroll
        for (int j = 0; j < 8; j++)
#pragma unroll
            for (int r = 0; r < 4; r++) acc[i][j][r] = 0.f;

    const int nchunks = K_ >> 6;

    auto load_tiles = [&](int k0, int buf) {
#pragma unroll
        for (int j = 0; j < 8; j++) {
            int idx = tid + j * 128;
            int r = idx >> 3, c = (idx & 7) << 3;           // halves
            CP16(sAs + (uint32_t)((buf * ABUF + r * STR + c) * 2),
                 Ap + (long)r * K_ + k0 + c);
        }
#pragma unroll
        for (int j = 0; j < 8; j++) {
            int idx = tid + j * 128;
            int r = idx >> 3, c = (idx & 7) << 3;
            CP16(sBs + (uint32_t)((buf * ABUF + r * STR + c) * 2),
                 Bp + (long)r * K_ + k0 + c);
        }
    };

    load_tiles(0, 0);
    CP_COMMIT();

    for (int ch = 0; ch < nchunks; ch++) {
        CP_WAIT(0);        // chunk ch's group (issued last iteration) complete
        __syncthreads();   // data visible; all warps done reading buf (ch+1)&1

        if (ch + 1 < nchunks) {
            load_tiles((ch + 1) << 6, (ch + 1) & 1);
            CP_COMMIT();   // proceeds in background during compute below
        }

        const uint32_t aBase = sAs + (uint32_t)((ch & 1) * ABUF * 2) + aOff;
        const uint32_t bBase = sBs + (uint32_t)((ch & 1) * ABUF * 2) + bOff;

        uint32_t ua[2][4][4], ub[2][4][4];
        // preload ks=0 fragments
#pragma unroll
        for (int mi = 0; mi < 4; mi++)
            LDSM4(ua[0][mi][0], ua[0][mi][1], ua[0][mi][2], ua[0][mi][3],
                  aBase + (uint32_t)(mi * 16 * STR * 2));
#pragma unroll
        for (int ni = 0; ni < 4; ni++)
            LDSM4(ub[0][ni][0], ub[0][ni][1], ub[0][ni][2], ub[0][ni][3],
                  bBase + (uint32_t)(ni * 16 * STR * 2));

#pragma unroll
        for (int ks = 0; ks < 4; ks++) {
            const int cur = ks & 1, nxt = cur ^ 1;
            if (ks < 3) {
#pragma unroll
                for (int mi = 0; mi < 4; mi++)
                    LDSM4(ua[nxt][mi][0], ua[nxt][mi][1], ua[nxt][mi][2], ua[nxt][mi][3],
                          aBase + (uint32_t)(mi * 16 * STR * 2 + (ks + 1) * 32));
#pragma unroll
                for (int ni = 0; ni < 4; ni++)
                    LDSM4(ub[nxt][ni][0], ub[nxt][ni][1], ub[nxt][ni][2], ub[nxt][ni][3],
                          bBase + (uint32_t)(ni * 16 * STR * 2 + (ks + 1) * 32));
            }
#pragma unroll
            for (int mi = 0; mi < 4; mi++)
#pragma unroll
                for (int ni = 0; ni < 4; ni++) {
                    MMA_BF16(acc[mi][2 * ni],     ua[cur][mi], ub[cur][ni][0], ub[cur][ni][1]);
                    MMA_BF16(acc[mi][2 * ni + 1], ua[cur][mi], ub[cur][ni][2], ub[cur][ni][3]);
                }
        }
    }

    // ---- epilogue: bias + activation ----
#pragma unroll
    for (int mi = 0; mi < 4; mi++) {
        const long r0 = m0 + wm * 64 + mi * 16 + lr;
#pragma unroll
        for (int ni = 0; ni < 8; ni++) {
            const int col = wn * 64 + ni * 8 + 2 * lc;
            const float bi0 = bp[col], bi1 = bp[col + 1];
            float v0 = act_f<ACT>(acc[mi][ni][0] + bi0);
            float v1 = act_f<ACT>(acc[mi][ni][1] + bi1);
            float v2 = act_f<ACT>(acc[mi][ni][2] + bi0);
            float v3 = act_f<ACT>(acc[mi][ni][3] + bi1);
            if (OUTBF) {
                bf16* Cp = (bf16*)Cv + (long)z * sC;
                *(__nv_bfloat162*)(Cp + r0 * N_ + n0 + col) =
                    __floats2bfloat162_rn(v0, v1);
                *(__nv_bfloat162*)(Cp + (r0 + 8) * N_ + n0 + col) =
                    __floats2bfloat162_rn(v2, v3);
            } else {
                float* Cp = (float*)Cv + (long)z * sC;
                *(float2*)(Cp + r0 * N_ + n0 + col)       = make_float2(v0, v1);
                *(float2*)(Cp + (r0 + 8) * N_ + n0 + col) = make_float2(v2, v3);
            }
        }
    }
}

static constexpr int SMEM_SZ = 4 * 128 * 72 * 2;   // 73728 B

// ---------------------------------------------------------------------------
// fp32 -> bf16 flat convert (n multiple of 4)
// ---------------------------------------------------------------------------
__global__ __launch_bounds__(256) void conv_bf16(
    const float* __restrict__ s, bf16* __restrict__ d, long n4)
{
    long i = (long)blockIdx.x * blockDim.x + threadIdx.x;
    if (i < n4) {
        float4 v = ((const float4*)s)[i];
        ((__nv_bfloat162*)d)[2 * i]     = __floats2bfloat162_rn(v.x, v.y);
        ((__nv_bfloat162*)d)[2 * i + 1] = __floats2bfloat162_rn(v.z, v.w);
    }
}

// ---------------------------------------------------------------------------
// fp32 [R,C] -> bf16 [C,R] transpose-convert (R,C multiples of 32), z-batched
// ---------------------------------------------------------------------------
__global__ __launch_bounds__(256) void transp_bf16(
    const float* __restrict__ src, bf16* __restrict__ dst,
    int R, int C, long sS, long sD)
{
    __shared__ float t[32][33];
    const float* s = src + (long)blockIdx.z * sS;
    bf16* d = dst + (long)blockIdx.z * sD;
    const int c0 = blockIdx.x * 32, r0 = blockIdx.y * 32;
    const int tx = threadIdx.x & 31, ty = threadIdx.x >> 5;   // 32 x 8
#pragma unroll
    for (int k = 0; k < 4; k++)
        t[ty + 8 * k][tx] = s[(long)(r0 + ty + 8 * k) * C + c0 + tx];
    __syncthreads();
#pragma unroll
    for (int k = 0; k < 4; k++)
        d[(long)(c0 + ty + 8 * k) * R + r0 + tx] = __float2bfloat16(t[tx][ty + 8 * k]);
}

// ---------------------------------------------------------------------------
// bc[n] = Wo[n,:] . bv + bo[n]
// ---------------------------------------------------------------------------
__global__ __launch_bounds__(256) void bc_k(
    const float* __restrict__ Wo, const float* __restrict__ bv,
    const float* __restrict__ bo, float* __restrict__ bc)
{
    const int n = blockIdx.x, tid = threadIdx.x;
    float s = 0.f;
    for (int j = tid; j < DDIM; j += 256) s += Wo[(long)n * DDIM + j] * bv[j];
#pragma unroll
    for (int o = 16; o > 0; o >>= 1) s += __shfl_xor_sync(0xffffffffu, s, o);
    __shared__ float r[8];
    if ((tid & 31) == 0) r[tid >> 5] = s;
    __syncthreads();
    if (tid == 0) {
        float tot = 0.f;
#pragma unroll
        for (int i = 0; i < 8; i++) tot += r[i];
        bc[n] = tot + bo[n];
    }
}

// ---------------------------------------------------------------------------
// Per-row LayerNorm (H=1024) + exact GELU, in place on bf16 h[M*B, H].
// 128 threads/row, 8 elems/thread, single-pass sum/sumsq, one sync.
// ---------------------------------------------------------------------------
__global__ __launch_bounds__(128) void ln_gelu_bf(
    bf16* __restrict__ h, const float* __restrict__ gamma,
    const float* __restrict__ beta)
{
    const long r = blockIdx.x;
    const int  m = (int)(r / BSZ);
    bf16* row = h + r * HDIM;
    const int tid = threadIdx.x;
    const int c0 = tid * 8;

    uint4 pk = *(const uint4*)(row + c0);
    float x[8];
    {
        __nv_bfloat162 q0 = *(__nv_bfloat162*)&pk.x;
        __nv_bfloat162 q1 = *(__nv_bfloat162*)&pk.y;
        __nv_bfloat162 q2 = *(__nv_bfloat162*)&pk.z;
        __nv_bfloat162 q3 = *(__nv_bfloat162*)&pk.w;
        x[0] = __bfloat162float(q0.x); x[1] = __bfloat162float(q0.y);
        x[2] = __bfloat162float(q1.x); x[3] = __bfloat162float(q1.y);
        x[4] = __bfloat162float(q2.x); x[5] = __bfloat162float(q2.y);
        x[6] = __bfloat162float(q3.x); x[7] = __bfloat162float(q3.y);
    }

    float s = 0.f, s2 = 0.f;
#pragma unroll
    for (int i = 0; i < 8; i++) { s += x[i]; s2 += x[i] * x[i]; }
#pragma unroll
    for (int o = 16; o > 0; o >>= 1) {
        s  += __shfl_xor_sync(0xffffffffu, s,  o);
        s2 += __shfl_xor_sync(0xffffffffu, s2, o);
    }
    __shared__ float sm1[4], sm2[4];
    if ((tid & 31) == 0) { sm1[tid >> 5] = s; sm2[tid >> 5] = s2; }
    __syncthreads();
    const float tot  = sm1[0] + sm1[1] + sm1[2] + sm1[3];
    const float tot2 = sm2[0] + sm2[1] + sm2[2] + sm2[3];
    const float mu   = tot * (1.0f / HDIM);
    const float var  = fmaxf(tot2 * (1.0f / HDIM) - mu * mu, 0.f);
    const float rstd = rsqrtf(var + 1e-5f);

    const float* gm = gamma + (long)m * HDIM + c0;
    const float* bm = beta  + (long)m * HDIM + c0;
    float4 g0 = *(const float4*)gm, g1 = *(const float4*)(gm + 4);
    float4 b0 = *(const float4*)bm, b1 = *(const float4*)(bm + 4);
    float g[8] = {g0.x, g0.y, g0.z, g0.w, g1.x, g1.y, g1.z, g1.w};
    float b[8] = {b0.x, b0.y, b0.z, b0.w, b1.x, b1.y, b1.z, b1.w};

    __nv_bfloat162 o2[4];
#pragma unroll
    for (int i = 0; i < 4; i++) {
        float t0 = (x[2 * i]     - mu) * rstd * g[2 * i]     + b[2 * i];
        float t1 = (x[2 * i + 1] - mu) * rstd * g[2 * i + 1] + b[2 * i + 1];
        t0 = 0.5f * t0 * (1.0f + erff(t0 * 0.70710678118654752f));
        t1 = 0.5f * t1 * (1.0f + erff(t1 * 0.70710678118654752f));
        o2[i] = __floats2bfloat162_rn(t0, t1);
    }
    *(uint4*)(row + c0) = *(uint4*)o2;
}

extern "C" void kernel_launch(void* const* d_in, const int* in_sizes, int n_in,
                              void* d_out, int out_size)
{
    const float* x     = (const float*)d_in[0];
    const float* in_w  = (const float*)d_in[1];   // [3D, D]
    const float* in_b  = (const float*)d_in[2];   // [3D]
    const float* out_w = (const float*)d_in[3];   // [D, D]
    const float* out_b = (const float*)d_in[4];   // [D]
    const float* W1    = (const float*)d_in[5];   // [M, D, H]
    const float* b1    = (const float*)d_in[6];   // [M, H]
    const float* ln_g  = (const float*)d_in[7];   // [M, H]
    const float* ln_b  = (const float*)d_in[8];   // [M, H]
    const float* W2    = (const float*)d_in[9];   // [M, H, H2]
    const float* b2    = (const float*)d_in[10];  // [M, H2]
    const float* W3    = (const float*)d_in[11];  // [M, H2, D]
    const float* b3    = (const float*)d_in[12];  // [M, D]
    float* out = (float*)d_out;                   // [M, B, D]

    bf16 *xb, *ab, *wvt, *wob, *wcb, *w1b, *w2b, *w3b, *h1b, *h2b;
    float *bc, *zeros;
    cudaGetSymbolAddress((void**)&xb,  g_xb);
    cudaGetSymbolAddress((void**)&ab,  g_ab);
    cudaGetSymbolAddress((void**)&wvt, g_wvt);
    cudaGetSymbolAddress((void**)&wob, g_wob);
    cudaGetSymbolAddress((void**)&wcb, g_wcb);
    cudaGetSymbolAddress((void**)&w1b, g_w1b);
    cudaGetSymbolAddress((void**)&w2b, g_w2b);
    cudaGetSymbolAddress((void**)&w3b, g_w3b);
    cudaGetSymbolAddress((void**)&h1b, g_h1b);
    cudaGetSymbolAddress((void**)&h2b, g_h2b);
    cudaGetSymbolAddress((void**)&bc,  g_bc);
    cudaGetSymbolAddress((void**)&zeros, g_zeros);

    cudaFuncSetAttribute(gemm_bf16<0, 1>, cudaFuncAttributeMaxDynamicSharedMemorySize, SMEM_SZ);
    cudaFuncSetAttribute(gemm_bf16<1, 1>, cudaFuncAttributeMaxDynamicSharedMemorySize, SMEM_SZ);
    cudaFuncSetAttribute(gemm_bf16<2, 0>, cudaFuncAttributeMaxDynamicSharedMemorySize, SMEM_SZ);

    // seq_len==1 => softmax over length-1 axis == 1 => attn == v.
    // a = x @ (Wo@Wv)^T + (Wo@bv + bo): fold both attention GEMMs into one.
    const float* Wv = in_w + (long)2 * DDIM * DDIM;
    const float* bv = in_b + 2 * DDIM;

    // --- prep: conversions ---
    conv_bf16<<<(BSZ * DDIM / 4 + 255) / 256, 256>>>(x, xb, BSZ * DDIM / 4);
    conv_bf16<<<(DDIM * DDIM / 4 + 255) / 256, 256>>>(out_w, wob, DDIM * DDIM / 4);
    transp_bf16<<<dim3(32, 32, 1), 256>>>(Wv, wvt, DDIM, DDIM, 0, 0);
    transp_bf16<<<dim3(32, 32, MMASK), 256>>>(W1, w1b, DDIM, HDIM,
        (long)DDIM * HDIM, (long)HDIM * DDIM);
    transp_bf16<<<dim3(16, 32, MMASK), 256>>>(W2, w2b, HDIM, H2DIM,
        (long)HDIM * H2DIM, (long)H2DIM * HDIM);
    transp_bf16<<<dim3(32, 16, MMASK), 256>>>(W3, w3b, H2DIM, DDIM,
        (long)H2DIM * DDIM, (long)DDIM * H2DIM);
    bc_k<<<DDIM, 256>>>(out_w, bv, out_b, bc);

    // Wc = Wo @ Wv  (bf16 out)
    gemm_bf16<0, 1><<<dim3(8, 8, 1), 128, SMEM_SZ>>>(
        wob, wvt, zeros, wcb, DDIM, DDIM, 0, 0, 0, 0);

    // a = x @ Wc^T + bc  (bf16 out)
    gemm_bf16<0, 1><<<dim3(8, 64, 1), 128, SMEM_SZ>>>(
        xb, wcb, bc, ab, DDIM, DDIM, 0, 0, 0, 0);

    // h1[m] = a @ W1[m] + b1[m]  (bf16 out)
    gemm_bf16<0, 1><<<dim3(8, 64, MMASK), 128, SMEM_SZ>>>(
        ab, w1b, b1, h1b, HDIM, DDIM,
        0, (long)HDIM * DDIM, (long)HDIM, (long)BSZ * HDIM);

    // LayerNorm + GELU in place (bf16)
    ln_gelu_bf<<<MMASK * BSZ, 128>>>(h1b, ln_g, ln_b);

    // h2[m] = gelu( h1[m] @ W2[m] + b2[m] )  (bf16 out)
    gemm_bf16<1, 1><<<dim3(4, 64, MMASK), 128, SMEM_SZ>>>(
        h1b, w2b, b2, h2b, H2DIM, HDIM,
        (long)BSZ * HDIM, (long)H2DIM * HDIM, (long)H2DIM, (long)BSZ * H2DIM);

    // out[m] = sigmoid( h2[m] @ W3[m] + b3[m] )  (f32 out)
    gemm_bf16<2, 0><<<dim3(8, 64, MMASK), 128, SMEM_SZ>>>(
        h2b, w3b, b3, out, DDIM, H2DIM,
        (long)BSZ * H2DIM, (long)DDIM * H2DIM, (long)DDIM, (long)BSZ * DDIM);
}

// round 10
// speedup vs baseline: 1.0925x; 1.0051x over previous
#include <cuda_runtime.h>
#include <cuda_bf16.h>
#include <cstdint>
#include <math.h>

#define BSZ   8192
#define DDIM  1024
#define HDIM  1024
#define H2DIM 512
#define MMASK 15

typedef __nv_bfloat16 bf16;

// ---------------------------------------------------------------------------
// Scratch (__device__ globals; no allocations allowed)
// ---------------------------------------------------------------------------
__device__ bf16  g_xb [BSZ * DDIM];
__device__ bf16  g_ab [BSZ * DDIM];
__device__ bf16  g_wvt[DDIM * DDIM];            // Wv^T  [c, j]
__device__ bf16  g_wob[DDIM * DDIM];            // Wo    [n, j]
__device__ bf16  g_wcb[DDIM * DDIM];            // Wc = Wo@Wv  [n, k]
__device__ bf16  g_w1b[MMASK * HDIM * DDIM];    // W1^T per m: [H, D]
__device__ bf16  g_w2b[MMASK * H2DIM * HDIM];   // W2^T per m: [H2, H]
__device__ bf16  g_w3b[MMASK * DDIM * H2DIM];   // W3^T per m: [D, H2]
__device__ bf16  g_h1b[MMASK * BSZ * HDIM];
__device__ bf16  g_h2b[MMASK * BSZ * H2DIM];
__device__ float g_bc [DDIM];
__device__ float g_zeros[DDIM];                 // stays zero (zero-initialized)

// ---------------------------------------------------------------------------
// helpers
// ---------------------------------------------------------------------------
__device__ __forceinline__ uint32_t smem_u32(const void* p) {
    uint32_t a;
    asm("{ .reg .u64 t; cvta.to.shared.u64 t, %1; cvt.u32.u64 %0, t; }"
        : "=r"(a) : "l"(p));
    return a;
}

#define CP16(saddr, gptr) \
    asm volatile("cp.async.cg.shared.global [%0], [%1], 16;" \
                 :: "r"(saddr), "l"(gptr) : "memory")
#define CP_COMMIT() asm volatile("cp.async.commit_group;" ::: "memory")
#define CP_WAIT(n)  asm volatile("cp.async.wait_group %0;" :: "n"(n) : "memory")

#define LDSM4(r0, r1, r2, r3, addr) \
    asm volatile("ldmatrix.sync.aligned.m8n8.x4.shared.b16 {%0,%1,%2,%3}, [%4];" \
                 : "=r"(r0), "=r"(r1), "=r"(r2), "=r"(r3) : "r"(addr))

// D += A(16x16) * B(16x8), bf16 inputs, f32 accum
#define MMA_BF16(d, a, b0, b1) \
    asm volatile("mma.sync.aligned.m16n8k16.row.col.f32.bf16.bf16.f32 " \
        "{%0,%1,%2,%3}, {%4,%5,%6,%7}, {%8,%9}, {%0,%1,%2,%3};" \
        : "+f"((d)[0]), "+f"((d)[1]), "+f"((d)[2]), "+f"((d)[3]) \
        : "r"((a)[0]), "r"((a)[1]), "r"((a)[2]), "r"((a)[3]), "r"(b0), "r"(b1))

template <int ACT>
__device__ __forceinline__ float act_f(float v) {
    if (ACT == 1) return 0.5f * v * (1.0f + erff(v * 0.70710678118654752f));
    if (ACT == 2) return 1.0f / (1.0f + expf(-v));
    return v;
}

// ---------------------------------------------------------------------------
// bf16 tensor-core GEMM:  C[z] = act( A[z] @ B[z]^T + bias[z] )
//   A: [M,K] bf16 row-major.  B: [N,K] bf16 row-major.  bias: f32 [N].
//   OUTBF=1 -> C bf16, else f32.  ACT: 0 none, 1 exact GELU, 2 sigmoid.
// CTA 128x128, BK=64, 128 threads = 4 warps (2x2), warp tile 64x64.
// 2-stage cp.async, one __syncthreads per chunk, register fragment
// double-buffering. Main loop is at the legacy-HMMA issue ceiling.
// Requires M%128==0, N%128==0, K%64==0.
// ---------------------------------------------------------------------------
template <int ACT, int OUTBF>
__global__ void __launch_bounds__(128, 2) gemm_bf16(
    const bf16* __restrict__ A, const bf16* __restrict__ Bw,
    const float* __restrict__ bias, void* __restrict__ Cv,
    int N_, int K_, long sA, long sB, long sBias, long sC)
{
    constexpr int STR  = 72;          // halves; 144B row stride (9x16B, conflict-free)
    constexpr int ABUF = 128 * STR;   // halves per buffer

    extern __shared__ __align__(16) bf16 smem[];
    bf16* As = smem;                  // [2][128][STR]
    bf16* Bs = smem + 2 * ABUF;       // [2][128][STR]
    const uint32_t sAs = smem_u32(As);
    const uint32_t sBs = smem_u32(Bs);

    const int tid  = threadIdx.x;
    const int lane = tid & 31;
    const int wid  = tid >> 5;
    const int lr = lane >> 2, lc = lane & 3;
    const int wm = wid >> 1, wn = wid & 1;

    const int z  = blockIdx.z;
    const int n0 = blockIdx.x * 128;
    const long m0 = (long)blockIdx.y * 128;
    const bf16* Ap = A + (long)z * sA + m0 * K_;
    const bf16* Bp = Bw + (long)z * sB + (long)n0 * K_;
    const float* bp = bias + (long)z * sBias + n0;

    // ldmatrix per-thread base offsets (bytes)
    const uint32_t aOff = (uint32_t)(((wm * 64 + (lane & 15)) * STR + (lane >> 4) * 8) * 2);
    const uint32_t bOff = (uint32_t)(((wn * 64 + ((lane >> 4) * 8 + (lane & 7))) * STR
                                      + ((lane >> 3) & 1) * 8) * 2);

    float acc[4][8][4];
#pragma unroll
    for (int i = 0; i < 4; i++)
#pragma unroll
        for (int j = 0; j < 8; j++)
#pragma unroll
            for (int r = 0; r < 4; r++) acc[i][j][r] = 0.f;

    const int nchunks = K_ >> 6;

    auto load_tiles = [&](int k0, int buf) {
#pragma unroll
        for (int j = 0; j < 8; j++) {
            int idx = tid + j * 128;
            int r = idx >> 3, c = (idx & 7) << 3;           // halves
            CP16(sAs + (uint32_t)((buf * ABUF + r * STR + c) * 2),
                 Ap + (long)r * K_ + k0 + c);
        }
#pragma unroll
        for (int j = 0; j < 8; j++) {
            int idx = tid + j * 128;
            int r = idx >> 3, c = (idx & 7) << 3;
            CP16(sBs + (uint32_t)((buf * ABUF + r * STR + c) * 2),
                 Bp + (long)r * K_ + k0 + c);
        }
    };

    load_tiles(0, 0);
    CP_COMMIT();

    for (int ch = 0; ch < nchunks; ch++) {
        CP_WAIT(0);        // chunk ch's group (issued last iteration) complete
        __syncthreads();   // data visible; all warps done reading buf (ch+1)&1

        if (ch + 1 < nchunks) {
            load_tiles((ch + 1) << 6, (ch + 1) & 1);
            CP_COMMIT();   // proceeds in background during compute below
        }

        const uint32_t aBase = sAs + (uint32_t)((ch & 1) * ABUF * 2) + aOff;
        const uint32_t bBase = sBs + (uint32_t)((ch & 1) * ABUF * 2) + bOff;

        uint32_t ua[2][4][4], ub[2][4][4];
        // preload ks=0 fragments
#pragma unroll
        for (int mi = 0; mi < 4; mi++)
            LDSM4(ua[0][mi][0], ua[0][mi][1], ua[0][mi][2], ua[0][mi][3],
                  aBase + (uint32_t)(mi * 16 * STR * 2));
#pragma unroll
        for (int ni = 0; ni < 4; ni++)
            LDSM4(ub[0][ni][0], ub[0][ni][1], ub[0][ni][2], ub[0][ni][3],
                  bBase + (uint32_t)(ni * 16 * STR * 2));

#pragma unroll
        for (int ks = 0; ks < 4; ks++) {
            const int cur = ks & 1, nxt = cur ^ 1;
            if (ks < 3) {
#pragma unroll
                for (int mi = 0; mi < 4; mi++)
                    LDSM4(ua[nxt][mi][0], ua[nxt][mi][1], ua[nxt][mi][2], ua[nxt][mi][3],
                          aBase + (uint32_t)(mi * 16 * STR * 2 + (ks + 1) * 32));
#pragma unroll
                for (int ni = 0; ni < 4; ni++)
                    LDSM4(ub[nxt][ni][0], ub[nxt][ni][1], ub[nxt][ni][2], ub[nxt][ni][3],
                          bBase + (uint32_t)(ni * 16 * STR * 2 + (ks + 1) * 32));
            }
#pragma unroll
            for (int mi = 0; mi < 4; mi++)
#pragma unroll
                for (int ni = 0; ni < 4; ni++) {
                    MMA_BF16(acc[mi][2 * ni],     ua[cur][mi], ub[cur][ni][0], ub[cur][ni][1]);
                    MMA_BF16(acc[mi][2 * ni + 1], ua[cur][mi], ub[cur][ni][2], ub[cur][ni][3]);
                }
        }
    }

    // ---- epilogue: bias + activation ----
#pragma unroll
    for (int mi = 0; mi < 4; mi++) {
        const long r0 = m0 + wm * 64 + mi * 16 + lr;
#pragma unroll
        for (int ni = 0; ni < 8; ni++) {
            const int col = wn * 64 + ni * 8 + 2 * lc;
            const float bi0 = bp[col], bi1 = bp[col + 1];
            float v0 = act_f<ACT>(acc[mi][ni][0] + bi0);
            float v1 = act_f<ACT>(acc[mi][ni][1] + bi1);
            float v2 = act_f<ACT>(acc[mi][ni][2] + bi0);
            float v3 = act_f<ACT>(acc[mi][ni][3] + bi1);
            if (OUTBF) {
                bf16* Cp = (bf16*)Cv + (long)z * sC;
                *(__nv_bfloat162*)(Cp + r0 * N_ + n0 + col) =
                    __floats2bfloat162_rn(v0, v1);
                *(__nv_bfloat162*)(Cp + (r0 + 8) * N_ + n0 + col) =
                    __floats2bfloat162_rn(v2, v3);
            } else {
                float* Cp = (float*)Cv + (long)z * sC;
                *(float2*)(Cp + r0 * N_ + n0 + col)       = make_float2(v0, v1);
                *(float2*)(Cp + (r0 + 8) * N_ + n0 + col) = make_float2(v2, v3);
            }
        }
    }
}

static constexpr int SMEM_SZ = 4 * 128 * 72 * 2;   // 73728 B

// ---------------------------------------------------------------------------
// ONE merged prep kernel: all fp32->bf16 converts, all transpose-converts,
// and the bc reduction, block-range specialized. Replaces 8 launches.
// Block ranges (256 threads each):
//   [0, 8192)         conv x            (8M elems as 2M float4)
//   [8192, 9216)      conv out_w -> wob (1M elems as 256K float4)
//   [9216, 10240)     transp Wv   [D,D] -> wvt
//   [10240, 25600)    transp W1   [D,H] per m -> w1b   (1024 blocks per m)
//   [25600, 33280)    transp W2   [H,H2] per m -> w2b  (512 blocks per m)
//   [33280, 40960)    transp W3   [H2,D] per m -> w3b  (512 blocks per m)
//   [40960, 41984)    bc[n] = Wo[n,:].bv + bo[n]
// ---------------------------------------------------------------------------
__device__ __forceinline__ void transp_tile(
    const float* __restrict__ s, bf16* __restrict__ d,
    int R, int C, int bx, int by, float (*t)[33])
{
    const int c0 = bx * 32, r0 = by * 32;
    const int tx = threadIdx.x & 31, ty = threadIdx.x >> 5;   // 32 x 8
#pragma unroll
    for (int k = 0; k < 4; k++)
        t[ty + 8 * k][tx] = s[(long)(r0 + ty + 8 * k) * C + c0 + tx];
    __syncthreads();
#pragma unroll
    for (int k = 0; k < 4; k++)
        d[(long)(c0 + ty + 8 * k) * R + r0 + tx] = __float2bfloat16(t[tx][ty + 8 * k]);
}

__global__ __launch_bounds__(256) void prep_all(
    const float* __restrict__ x,  const float* __restrict__ out_w,
    const float* __restrict__ Wv, const float* __restrict__ bv,
    const float* __restrict__ bo,
    const float* __restrict__ W1, const float* __restrict__ W2,
    const float* __restrict__ W3,
    bf16* __restrict__ xb,  bf16* __restrict__ wob, bf16* __restrict__ wvt,
    bf16* __restrict__ w1b, bf16* __restrict__ w2b, bf16* __restrict__ w3b,
    float* __restrict__ bc)
{
    __shared__ float t[32][33];
    const int b = blockIdx.x;
    const int tid = threadIdx.x;

    if (b < 8192) {                       // conv x
        long i = (long)b * 256 + tid;
        float4 v = ((const float4*)x)[i];
        ((__nv_bfloat162*)xb)[2 * i]     = __floats2bfloat162_rn(v.x, v.y);
        ((__nv_bfloat162*)xb)[2 * i + 1] = __floats2bfloat162_rn(v.z, v.w);
    } else if (b < 9216) {                // conv out_w
        long i = (long)(b - 8192) * 256 + tid;
        float4 v = ((const float4*)out_w)[i];
        ((__nv_bfloat162*)wob)[2 * i]     = __floats2bfloat162_rn(v.x, v.y);
        ((__nv_bfloat162*)wob)[2 * i + 1] = __floats2bfloat162_rn(v.z, v.w);
    } else if (b < 10240) {               // transp Wv [D,D]
        int r = b - 9216;                 // 32 x 32
        transp_tile(Wv, wvt, DDIM, DDIM, r & 31, r >> 5, t);
    } else if (b < 25600) {               // transp W1 [D,H] per m
        int r = b - 10240;
        int m = r >> 10; r &= 1023;       // 1024 blocks per m (32 x 32)
        transp_tile(W1 + (long)m * DDIM * HDIM, w1b + (long)m * HDIM * DDIM,
                    DDIM, HDIM, r & 31, r >> 5, t);
    } else if (b < 33280) {               // transp W2 [H,H2] per m
        int r = b - 25600;
        int m = r >> 9; r &= 511;         // 512 blocks per m (16 x 32)
        transp_tile(W2 + (long)m * HDIM * H2DIM, w2b + (long)m * H2DIM * HDIM,
                    HDIM, H2DIM, r & 15, r >> 4, t);
    } else if (b < 40960) {               // transp W3 [H2,D] per m
        int r = b - 33280;
        int m = r >> 9; r &= 511;         // 512 blocks per m (32 x 16)
        transp_tile(W3 + (long)m * H2DIM * DDIM, w3b + (long)m * DDIM * H2DIM,
                    H2DIM, DDIM, r & 31, r >> 5, t);
    } else {                              // bc[n] = Wo[n,:].bv + bo[n]
        const int n = b - 40960;
        float s = 0.f;
        for (int j = tid; j < DDIM; j += 256) s += out_w[(long)n * DDIM + j] * bv[j];
#pragma unroll
        for (int o = 16; o > 0; o >>= 1) s += __shfl_xor_sync(0xffffffffu, s, o);
        if ((tid & 31) == 0) t[0][tid >> 5] = s;
        __syncthreads();
        if (tid == 0) {
            float tot = 0.f;
#pragma unroll
            for (int i = 0; i < 8; i++) tot += t[0][i];
            bc[n] = tot + bo[n];
        }
    }
}

// ---------------------------------------------------------------------------
// Per-row LayerNorm (H=1024) + exact GELU, in place on bf16 h[M*B, H].
// 128 threads/row, 8 elems/thread, single-pass sum/sumsq, one sync.
// ---------------------------------------------------------------------------
__global__ __launch_bounds__(128) void ln_gelu_bf(
    bf16* __restrict__ h, const float* __restrict__ gamma,
    const float* __restrict__ beta)
{
    const long r = blockIdx.x;
    const int  m = (int)(r / BSZ);
    bf16* row = h + r * HDIM;
    const int tid = threadIdx.x;
    const int c0 = tid * 8;

    uint4 pk = *(const uint4*)(row + c0);
    float x[8];
    {
        __nv_bfloat162 q0 = *(__nv_bfloat162*)&pk.x;
        __nv_bfloat162 q1 = *(__nv_bfloat162*)&pk.y;
        __nv_bfloat162 q2 = *(__nv_bfloat162*)&pk.z;
        __nv_bfloat162 q3 = *(__nv_bfloat162*)&pk.w;
        x[0] = __bfloat162float(q0.x); x[1] = __bfloat162float(q0.y);
        x[2] = __bfloat162float(q1.x); x[3] = __bfloat162float(q1.y);
        x[4] = __bfloat162float(q2.x); x[5] = __bfloat162float(q2.y);
        x[6] = __bfloat162float(q3.x); x[7] = __bfloat162float(q3.y);
    }

    float s = 0.f, s2 = 0.f;
#pragma unroll
    for (int i = 0; i < 8; i++) { s += x[i]; s2 += x[i] * x[i]; }
#pragma unroll
    for (int o = 16; o > 0; o >>= 1) {
        s  += __shfl_xor_sync(0xffffffffu, s,  o);
        s2 += __shfl_xor_sync(0xffffffffu, s2, o);
    }
    __shared__ float sm1[4], sm2[4];
    if ((tid & 31) == 0) { sm1[tid >> 5] = s; sm2[tid >> 5] = s2; }
    __syncthreads();
    const float tot  = sm1[0] + sm1[1] + sm1[2] + sm1[3];
    const float tot2 = sm2[0] + sm2[1] + sm2[2] + sm2[3];
    const float mu   = tot * (1.0f / HDIM);
    const float var  = fmaxf(tot2 * (1.0f / HDIM) - mu * mu, 0.f);
    const float rstd = rsqrtf(var + 1e-5f);

    const float* gm = gamma + (long)m * HDIM + c0;
    const float* bm = beta  + (long)m * HDIM + c0;
    float4 g0 = *(const float4*)gm, g1 = *(const float4*)(gm + 4);
    float4 b0 = *(const float4*)bm, b1 = *(const float4*)(bm + 4);
    float g[8] = {g0.x, g0.y, g0.z, g0.w, g1.x, g1.y, g1.z, g1.w};
    float b[8] = {b0.x, b0.y, b0.z, b0.w, b1.x, b1.y, b1.z, b1.w};

    __nv_bfloat162 o2[4];
#pragma unroll
    for (int i = 0; i < 4; i++) {
        float t0 = (x[2 * i]     - mu) * rstd * g[2 * i]     + b[2 * i];
        float t1 = (x[2 * i + 1] - mu) * rstd * g[2 * i + 1] + b[2 * i + 1];
        t0 = 0.5f * t0 * (1.0f + erff(t0 * 0.70710678118654752f));
        t1 = 0.5f * t1 * (1.0f + erff(t1 * 0.70710678118654752f));
        o2[i] = __floats2bfloat162_rn(t0, t1);
    }
    *(uint4*)(row + c0) = *(uint4*)o2;
}

extern "C" void kernel_launch(void* const* d_in, const int* in_sizes, int n_in,
                              void* d_out, int out_size)
{
    const float* x     = (const float*)d_in[0];
    const float* in_w  = (const float*)d_in[1];   // [3D, D]
    const float* in_b  = (const float*)d_in[2];   // [3D]
    const float* out_w = (const float*)d_in[3];   // [D, D]
    const float* out_b = (const float*)d_in[4];   // [D]
    const float* W1    = (const float*)d_in[5];   // [M, D, H]
    const float* b1    = (const float*)d_in[6];   // [M, H]
    const float* ln_g  = (const float*)d_in[7];   // [M, H]
    const float* ln_b  = (const float*)d_in[8];   // [M, H]
    const float* W2    = (const float*)d_in[9];   // [M, H, H2]
    const float* b2    = (const float*)d_in[10];  // [M, H2]
    const float* W3    = (const float*)d_in[11];  // [M, H2, D]
    const float* b3    = (const float*)d_in[12];  // [M, D]
    float* out = (float*)d_out;                   // [M, B, D]

    bf16 *xb, *ab, *wvt, *wob, *wcb, *w1b, *w2b, *w3b, *h1b, *h2b;
    float *bc, *zeros;
    cudaGetSymbolAddress((void**)&xb,  g_xb);
    cudaGetSymbolAddress((void**)&ab,  g_ab);
    cudaGetSymbolAddress((void**)&wvt, g_wvt);
    cudaGetSymbolAddress((void**)&wob, g_wob);
    cudaGetSymbolAddress((void**)&wcb, g_wcb);
    cudaGetSymbolAddress((void**)&w1b, g_w1b);
    cudaGetSymbolAddress((void**)&w2b, g_w2b);
    cudaGetSymbolAddress((void**)&w3b, g_w3b);
    cudaGetSymbolAddress((void**)&h1b, g_h1b);
    cudaGetSymbolAddress((void**)&h2b, g_h2b);
    cudaGetSymbolAddress((void**)&bc,  g_bc);
    cudaGetSymbolAddress((void**)&zeros, g_zeros);

    cudaFuncSetAttribute(gemm_bf16<0, 1>, cudaFuncAttributeMaxDynamicSharedMemorySize, SMEM_SZ);
    cudaFuncSetAttribute(gemm_bf16<1, 1>, cudaFuncAttributeMaxDynamicSharedMemorySize, SMEM_SZ);
    cudaFuncSetAttribute(gemm_bf16<2, 0>, cudaFuncAttributeMaxDynamicSharedMemorySize, SMEM_SZ);

    // seq_len==1 => softmax over length-1 axis == 1 => attn == v.
    // a = x @ (Wo@Wv)^T + (Wo@bv + bo): fold both attention GEMMs into one.
    const float* Wv = in_w + (long)2 * DDIM * DDIM;
    const float* bv = in_b + 2 * DDIM;

    // --- all prep in ONE launch ---
    prep_all<<<41984, 256>>>(x, out_w, Wv, bv, out_b, W1, W2, W3,
                             xb, wob, wvt, w1b, w2b, w3b, bc);

    // Wc = Wo @ Wv  (bf16 out)
    gemm_bf16<0, 1><<<dim3(8, 8, 1), 128, SMEM_SZ>>>(
        wob, wvt, zeros, wcb, DDIM, DDIM, 0, 0, 0, 0);

    // a = x @ Wc^T + bc  (bf16 out)
    gemm_bf16<0, 1><<<dim3(8, 64, 1), 128, SMEM_SZ>>>(
        xb, wcb, bc, ab, DDIM, DDIM, 0, 0, 0, 0);

    // h1[m] = a @ W1[m] + b1[m]  (bf16 out)
    gemm_bf16<0, 1><<<dim3(8, 64, MMASK), 128, SMEM_SZ>>>(
        ab, w1b, b1, h1b, HDIM, DDIM,
        0, (long)HDIM * DDIM, (long)HDIM, (long)BSZ * HDIM);

    // LayerNorm + GELU in place (bf16)
    ln_gelu_bf<<<MMASK * BSZ, 128>>>(h1b, ln_g, ln_b);

    // h2[m] = gelu( h1[m] @ W2[m] + b2[m] )  (bf16 out)
    gemm_bf16<1, 1><<<dim3(4, 64, MMASK), 128, SMEM_SZ>>>(
        h1b, w2b, b2, h2b, H2DIM, HDIM,
        (long)BSZ * HDIM, (long)H2DIM * HDIM, (long)H2DIM, (long)BSZ * H2DIM);

    // out[m] = sigmoid( h2[m] @ W3[m] + b3[m] )  (f32 out)
    gemm_bf16<2, 0><<<dim3(8, 64, MMASK), 128, SMEM_SZ>>>(
        h2b, w3b, b3, out, DDIM, H2DIM,
        (long)BSZ * H2DIM, (long)DDIM * H2DIM, (long)DDIM, (long)BSZ * DDIM);
}

// round 11
// speedup vs baseline: 1.1517x; 1.0542x over previous
#include <cuda_runtime.h>
#include <cuda_bf16.h>
#include <cstdint>
#include <math.h>

#define BSZ   8192
#define DDIM  1024
#define HDIM  1024
#define H2DIM 512
#define MMASK 15

typedef __nv_bfloat16 bf16;

// ---------------------------------------------------------------------------
// Scratch (__device__ globals; no allocations allowed)
// ---------------------------------------------------------------------------
__device__ bf16  g_xb [BSZ * DDIM];
__device__ bf16  g_ab [BSZ * DDIM];
__device__ bf16  g_wvt[DDIM * DDIM];            // Wv^T  [c, j]
__device__ bf16  g_wob[DDIM * DDIM];            // Wo    [n, j]
__device__ bf16  g_wcb[DDIM * DDIM];            // Wc = Wo@Wv  [n, k]
__device__ bf16  g_w1b[MMASK * HDIM * DDIM];    // W1^T per m: [H, D]
__device__ bf16  g_w2b[MMASK * H2DIM * HDIM];   // W2^T per m: [H2, H]
__device__ bf16  g_w3b[MMASK * DDIM * H2DIM];   // W3^T per m: [D, H2]
__device__ bf16  g_h1b[MMASK * BSZ * HDIM];
__device__ bf16  g_h2b[MMASK * BSZ * H2DIM];
__device__ float g_bc [DDIM];
__device__ float g_zeros[DDIM];                 // stays zero (zero-initialized)

// ---------------------------------------------------------------------------
// helpers
// ---------------------------------------------------------------------------
__device__ __forceinline__ uint32_t smem_u32(const void* p) {
    uint32_t a;
    asm("{ .reg .u64 t; cvta.to.shared.u64 t, %1; cvt.u32.u64 %0, t; }"
        : "=r"(a) : "l"(p));
    return a;
}

#define CP16(saddr, gptr) \
    asm volatile("cp.async.cg.shared.global [%0], [%1], 16;" \
                 :: "r"(saddr), "l"(gptr) : "memory")
#define CP_COMMIT() asm volatile("cp.async.commit_group;" ::: "memory")
#define CP_WAIT(n)  asm volatile("cp.async.wait_group %0;" :: "n"(n) : "memory")

#define LDSM4(r0, r1, r2, r3, addr) \
    asm volatile("ldmatrix.sync.aligned.m8n8.x4.shared.b16 {%0,%1,%2,%3}, [%4];" \
                 : "=r"(r0), "=r"(r1), "=r"(r2), "=r"(r3) : "r"(addr))

// D += A(16x16) * B(16x8), bf16 inputs, f32 accum
#define MMA_BF16(d, a, b0, b1) \
    asm volatile("mma.sync.aligned.m16n8k16.row.col.f32.bf16.bf16.f32 " \
        "{%0,%1,%2,%3}, {%4,%5,%6,%7}, {%8,%9}, {%0,%1,%2,%3};" \
        : "+f"((d)[0]), "+f"((d)[1]), "+f"((d)[2]), "+f"((d)[3]) \
        : "r"((a)[0]), "r"((a)[1]), "r"((a)[2]), "r"((a)[3]), "r"(b0), "r"(b1))

template <int ACT>
__device__ __forceinline__ float act_f(float v) {
    if (ACT == 1) return 0.5f * v * (1.0f + erff(v * 0.70710678118654752f));
    if (ACT == 2) return 1.0f / (1.0f + expf(-v));
    return v;
}

// ---------------------------------------------------------------------------
// bf16 tensor-core GEMM:  C[z] = act( A[z] @ B[z]^T + bias[z] )
//   A: [M,K] bf16 row-major.  B: [N,K] bf16 row-major.  bias: f32 [N].
//   OUTBF=1 -> C bf16, else f32.  ACT: 0 none, 1 exact GELU, 2 sigmoid.
// CTA 128x128, BK=64, 256 threads = 8 warps (2x4), warp tile 64x32.
// R10 ncu showed tensor=60.9% at 2 warps/SMSP (128-thread CTAs, 238 regs).
// 8 smaller warps cut regs to ~110 -> 2 CTAs/SM -> 4 warps/SMSP to hide
// barrier/LDSM bubbles. 2-stage cp.async, one __syncthreads per chunk.
// Requires M%128==0, N%128==0, K%64==0.
// ---------------------------------------------------------------------------
template <int ACT, int OUTBF>
__global__ void __launch_bounds__(256, 2) gemm_bf16(
    const bf16* __restrict__ A, const bf16* __restrict__ Bw,
    const float* __restrict__ bias, void* __restrict__ Cv,
    int N_, int K_, long sA, long sB, long sBias, long sC)
{
    constexpr int STR  = 72;          // halves; 144B row stride (9x16B, conflict-free)
    constexpr int ABUF = 128 * STR;   // halves per buffer

    extern __shared__ __align__(16) bf16 smem[];
    bf16* As = smem;                  // [2][128][STR]
    bf16* Bs = smem + 2 * ABUF;       // [2][128][STR]
    const uint32_t sAs = smem_u32(As);
    const uint32_t sBs = smem_u32(Bs);

    const int tid  = threadIdx.x;
    const int lane = tid & 31;
    const int wid  = tid >> 5;
    const int lr = lane >> 2, lc = lane & 3;
    const int wm = wid >> 2;          // 0..1  (64-row band)
    const int wn = wid & 3;           // 0..3  (32-col band)

    const int z  = blockIdx.z;
    const int n0 = blockIdx.x * 128;
    const long m0 = (long)blockIdx.y * 128;
    const bf16* Ap = A + (long)z * sA + m0 * K_;
    const bf16* Bp = Bw + (long)z * sB + (long)n0 * K_;
    const float* bp = bias + (long)z * sBias + n0;

    // ldmatrix per-thread base offsets (bytes)
    const uint32_t aOff = (uint32_t)(((wm * 64 + (lane & 15)) * STR + (lane >> 4) * 8) * 2);
    const uint32_t bOff = (uint32_t)(((wn * 32 + ((lane >> 4) * 8 + (lane & 7))) * STR
                                      + ((lane >> 3) & 1) * 8) * 2);

    float acc[4][4][4];
#pragma unroll
    for (int i = 0; i < 4; i++)
#pragma unroll
        for (int j = 0; j < 4; j++)
#pragma unroll
            for (int r = 0; r < 4; r++) acc[i][j][r] = 0.f;

    const int nchunks = K_ >> 6;

    auto load_tiles = [&](int k0, int buf) {
#pragma unroll
        for (int j = 0; j < 4; j++) {
            int idx = tid + j * 256;
            int r = idx >> 3, c = (idx & 7) << 3;           // halves
            CP16(sAs + (uint32_t)((buf * ABUF + r * STR + c) * 2),
                 Ap + (long)r * K_ + k0 + c);
        }
#pragma unroll
        for (int j = 0; j < 4; j++) {
            int idx = tid + j * 256;
            int r = idx >> 3, c = (idx & 7) << 3;
            CP16(sBs + (uint32_t)((buf * ABUF + r * STR + c) * 2),
                 Bp + (long)r * K_ + k0 + c);
        }
    };

    load_tiles(0, 0);
    CP_COMMIT();

    for (int ch = 0; ch < nchunks; ch++) {
        CP_WAIT(0);        // chunk ch's group (issued last iteration) complete
        __syncthreads();   // data visible; all warps done reading buf (ch+1)&1

        if (ch + 1 < nchunks) {
            load_tiles((ch + 1) << 6, (ch + 1) & 1);
            CP_COMMIT();   // proceeds in background during compute below
        }

        const uint32_t aBase = sAs + (uint32_t)((ch & 1) * ABUF * 2) + aOff;
        const uint32_t bBase = sBs + (uint32_t)((ch & 1) * ABUF * 2) + bOff;

#pragma unroll
        for (int ks = 0; ks < 4; ks++) {
            uint32_t ua[4][4], ub[2][4];
#pragma unroll
            for (int mi = 0; mi < 4; mi++)
                LDSM4(ua[mi][0], ua[mi][1], ua[mi][2], ua[mi][3],
                      aBase + (uint32_t)(mi * 16 * STR * 2 + ks * 32));
#pragma unroll
            for (int ni2 = 0; ni2 < 2; ni2++)
                LDSM4(ub[ni2][0], ub[ni2][1], ub[ni2][2], ub[ni2][3],
                      bBase + (uint32_t)(ni2 * 16 * STR * 2 + ks * 32));
#pragma unroll
            for (int mi = 0; mi < 4; mi++)
#pragma unroll
                for (int ni2 = 0; ni2 < 2; ni2++) {
                    MMA_BF16(acc[mi][2 * ni2],     ua[mi], ub[ni2][0], ub[ni2][1]);
                    MMA_BF16(acc[mi][2 * ni2 + 1], ua[mi], ub[ni2][2], ub[ni2][3]);
                }
        }
    }

    // ---- epilogue: bias + activation ----
#pragma unroll
    for (int mi = 0; mi < 4; mi++) {
        const long r0 = m0 + wm * 64 + mi * 16 + lr;
#pragma unroll
        for (int ni = 0; ni < 4; ni++) {
            const int col = wn * 32 + ni * 8 + 2 * lc;
            const float bi0 = bp[col], bi1 = bp[col + 1];
            float v0 = act_f<ACT>(acc[mi][ni][0] + bi0);
            float v1 = act_f<ACT>(acc[mi][ni][1] + bi1);
            float v2 = act_f<ACT>(acc[mi][ni][2] + bi0);
            float v3 = act_f<ACT>(acc[mi][ni][3] + bi1);
            if (OUTBF) {
                bf16* Cp = (bf16*)Cv + (long)z * sC;
                *(__nv_bfloat162*)(Cp + r0 * N_ + n0 + col) =
                    __floats2bfloat162_rn(v0, v1);
                *(__nv_bfloat162*)(Cp + (r0 + 8) * N_ + n0 + col) =
                    __floats2bfloat162_rn(v2, v3);
            } else {
                float* Cp = (float*)Cv + (long)z * sC;
                *(float2*)(Cp + r0 * N_ + n0 + col)       = make_float2(v0, v1);
                *(float2*)(Cp + (r0 + 8) * N_ + n0 + col) = make_float2(v2, v3);
            }
        }
    }
}

static constexpr int SMEM_SZ = 4 * 128 * 72 * 2;   // 73728 B

// ---------------------------------------------------------------------------
// ONE merged prep kernel: all fp32->bf16 converts, all transpose-converts,
// and the bc reduction, block-range specialized. Replaces 8 launches.
// ---------------------------------------------------------------------------
__device__ __forceinline__ void transp_tile(
    const float* __restrict__ s, bf16* __restrict__ d,
    int R, int C, int bx, int by, float (*t)[33])
{
    const int c0 = bx * 32, r0 = by * 32;
    const int tx = threadIdx.x & 31, ty = threadIdx.x >> 5;   // 32 x 8
#pragma unroll
    for (int k = 0; k < 4; k++)
        t[ty + 8 * k][tx] = s[(long)(r0 + ty + 8 * k) * C + c0 + tx];
    __syncthreads();
#pragma unroll
    for (int k = 0; k < 4; k++)
        d[(long)(c0 + ty + 8 * k) * R + r0 + tx] = __float2bfloat16(t[tx][ty + 8 * k]);
}

__global__ __launch_bounds__(256) void prep_all(
    const float* __restrict__ x,  const float* __restrict__ out_w,
    const float* __restrict__ Wv, const float* __restrict__ bv,
    const float* __restrict__ bo,
    const float* __restrict__ W1, const float* __restrict__ W2,
    const float* __restrict__ W3,
    bf16* __restrict__ xb,  bf16* __restrict__ wob, bf16* __restrict__ wvt,
    bf16* __restrict__ w1b, bf16* __restrict__ w2b, bf16* __restrict__ w3b,
    float* __restrict__ bc)
{
    __shared__ float t[32][33];
    const int b = blockIdx.x;
    const int tid = threadIdx.x;

    if (b < 8192) {                       // conv x
        long i = (long)b * 256 + tid;
        float4 v = ((const float4*)x)[i];
        ((__nv_bfloat162*)xb)[2 * i]     = __floats2bfloat162_rn(v.x, v.y);
        ((__nv_bfloat162*)xb)[2 * i + 1] = __floats2bfloat162_rn(v.z, v.w);
    } else if (b < 9216) {                // conv out_w
        long i = (long)(b - 8192) * 256 + tid;
        float4 v = ((const float4*)out_w)[i];
        ((__nv_bfloat162*)wob)[2 * i]     = __floats2bfloat162_rn(v.x, v.y);
        ((__nv_bfloat162*)wob)[2 * i + 1] = __floats2bfloat162_rn(v.z, v.w);
    } else if (b < 10240) {               // transp Wv [D,D]
        int r = b - 9216;                 // 32 x 32
        transp_tile(Wv, wvt, DDIM, DDIM, r & 31, r >> 5, t);
    } else if (b < 25600) {               // transp W1 [D,H] per m
        int r = b - 10240;
        int m = r >> 10; r &= 1023;       // 1024 blocks per m (32 x 32)
        transp_tile(W1 + (long)m * DDIM * HDIM, w1b + (long)m * HDIM * DDIM,
                    DDIM, HDIM, r & 31, r >> 5, t);
    } else if (b < 33280) {               // transp W2 [H,H2] per m
        int r = b - 25600;
        int m = r >> 9; r &= 511;         // 512 blocks per m (16 x 32)
        transp_tile(W2 + (long)m * HDIM * H2DIM, w2b + (long)m * H2DIM * HDIM,
                    HDIM, H2DIM, r & 15, r >> 4, t);
    } else if (b < 40960) {               // transp W3 [H2,D] per m
        int r = b - 33280;
        int m = r >> 9; r &= 511;         // 512 blocks per m (32 x 16)
        transp_tile(W3 + (long)m * H2DIM * DDIM, w3b + (long)m * DDIM * H2DIM,
                    H2DIM, DDIM, r & 31, r >> 5, t);
    } else {                              // bc[n] = Wo[n,:].bv + bo[n]
        const int n = b - 40960;
        float s = 0.f;
        for (int j = tid; j < DDIM; j += 256) s += out_w[(long)n * DDIM + j] * bv[j];
#pragma unroll
        for (int o = 16; o > 0; o >>= 1) s += __shfl_xor_sync(0xffffffffu, s, o);
        if ((tid & 31) == 0) t[0][tid >> 5] = s;
        __syncthreads();
        if (tid == 0) {
            float tot = 0.f;
#pragma unroll
            for (int i = 0; i < 8; i++) tot += t[0][i];
            bc[n] = tot + bo[n];
        }
    }
}

// ---------------------------------------------------------------------------
// Per-row LayerNorm (H=1024) + exact GELU, in place on bf16 h[M*B, H].
// 128 threads/row, 8 elems/thread, single-pass sum/sumsq, one sync.
// ---------------------------------------------------------------------------
__global__ __launch_bounds__(128) void ln_gelu_bf(
    bf16* __restrict__ h, const float* __restrict__ gamma,
    const float* __restrict__ beta)
{
    const long r = blockIdx.x;
    const int  m = (int)(r / BSZ);
    bf16* row = h + r * HDIM;
    const int tid = threadIdx.x;
    const int c0 = tid * 8;

    uint4 pk = *(const uint4*)(row + c0);
    float x[8];
    {
        __nv_bfloat162 q0 = *(__nv_bfloat162*)&pk.x;
        __nv_bfloat162 q1 = *(__nv_bfloat162*)&pk.y;
        __nv_bfloat162 q2 = *(__nv_bfloat162*)&pk.z;
        __nv_bfloat162 q3 = *(__nv_bfloat162*)&pk.w;
        x[0] = __bfloat162float(q0.x); x[1] = __bfloat162float(q0.y);
        x[2] = __bfloat162float(q1.x); x[3] = __bfloat162float(q1.y);
        x[4] = __bfloat162float(q2.x); x[5] = __bfloat162float(q2.y);
        x[6] = __bfloat162float(q3.x); x[7] = __bfloat162float(q3.y);
    }

    float s = 0.f, s2 = 0.f;
#pragma unroll
    for (int i = 0; i < 8; i++) { s += x[i]; s2 += x[i] * x[i]; }
#pragma unroll
    for (int o = 16; o > 0; o >>= 1) {
        s  += __shfl_xor_sync(0xffffffffu, s,  o);
        s2 += __shfl_xor_sync(0xffffffffu, s2, o);
    }
    __shared__ float sm1[4], sm2[4];
    if ((tid & 31) == 0) { sm1[tid >> 5] = s; sm2[tid >> 5] = s2; }
    __syncthreads();
    const float tot  = sm1[0] + sm1[1] + sm1[2] + sm1[3];
    const float tot2 = sm2[0] + sm2[1] + sm2[2] + sm2[3];
    const float mu   = tot * (1.0f / HDIM);
    const float var  = fmaxf(tot2 * (1.0f / HDIM) - mu * mu, 0.f);
    const float rstd = rsqrtf(var + 1e-5f);

    const float* gm = gamma + (long)m * HDIM + c0;
    const float* bm = beta  + (long)m * HDIM + c0;
    float4 g0 = *(const float4*)gm, g1 = *(const float4*)(gm + 4);
    float4 b0 = *(const float4*)bm, b1 = *(const float4*)(bm + 4);
    float g[8] = {g0.x, g0.y, g0.z, g0.w, g1.x, g1.y, g1.z, g1.w};
    float b[8] = {b0.x, b0.y, b0.z, b0.w, b1.x, b1.y, b1.z, b1.w};

    __nv_bfloat162 o2[4];
#pragma unroll
    for (int i = 0; i < 4; i++) {
        float t0 = (x[2 * i]     - mu) * rstd * g[2 * i]     + b[2 * i];
        float t1 = (x[2 * i + 1] - mu) * rstd * g[2 * i + 1] + b[2 * i + 1];
        t0 = 0.5f * t0 * (1.0f + erff(t0 * 0.70710678118654752f));
        t1 = 0.5f * t1 * (1.0f + erff(t1 * 0.70710678118654752f));
        o2[i] = __floats2bfloat162_rn(t0, t1);
    }
    *(uint4*)(row + c0) = *(uint4*)o2;
}

extern "C" void kernel_launch(void* const* d_in, const int* in_sizes, int n_in,
                              void* d_out, int out_size)
{
    const float* x     = (const float*)d_in[0];
    const float* in_w  = (const float*)d_in[1];   // [3D, D]
    const float* in_b  = (const float*)d_in[2];   // [3D]
    const float* out_w = (const float*)d_in[3];   // [D, D]
    const float* out_b = (const float*)d_in[4];   // [D]
    const float* W1    = (const float*)d_in[5];   // [M, D, H]
    const float* b1    = (const float*)d_in[6];   // [M, H]
    const float* ln_g  = (const float*)d_in[7];   // [M, H]
    const float* ln_b  = (const float*)d_in[8];   // [M, H]
    const float* W2    = (const float*)d_in[9];   // [M, H, H2]
    const float* b2    = (const float*)d_in[10];  // [M, H2]
    const float* W3    = (const float*)d_in[11];  // [M, H2, D]
    const float* b3    = (const float*)d_in[12];  // [M, D]
    float* out = (float*)d_out;                   // [M, B, D]

    bf16 *xb, *ab, *wvt, *wob, *wcb, *w1b, *w2b, *w3b, *h1b, *h2b;
    float *bc, *zeros;
    cudaGetSymbolAddress((void**)&xb,  g_xb);
    cudaGetSymbolAddress((void**)&ab,  g_ab);
    cudaGetSymbolAddress((void**)&wvt, g_wvt);
    cudaGetSymbolAddress((void**)&wob, g_wob);
    cudaGetSymbolAddress((void**)&wcb, g_wcb);
    cudaGetSymbolAddress((void**)&w1b, g_w1b);
    cudaGetSymbolAddress((void**)&w2b, g_w2b);
    cudaGetSymbolAddress((void**)&w3b, g_w3b);
    cudaGetSymbolAddress((void**)&h1b, g_h1b);
    cudaGetSymbolAddress((void**)&h2b, g_h2b);
    cudaGetSymbolAddress((void**)&bc,  g_bc);
    cudaGetSymbolAddress((void**)&zeros, g_zeros);

    cudaFuncSetAttribute(gemm_bf16<0, 1>, cudaFuncAttributeMaxDynamicSharedMemorySize, SMEM_SZ);
    cudaFuncSetAttribute(gemm_bf16<1, 1>, cudaFuncAttributeMaxDynamicSharedMemorySize, SMEM_SZ);
    cudaFuncSetAttribute(gemm_bf16<2, 0>, cudaFuncAttributeMaxDynamicSharedMemorySize, SMEM_SZ);

    // seq_len==1 => softmax over length-1 axis == 1 => attn == v.
    // a = x @ (Wo@Wv)^T + (Wo@bv + bo): fold both attention GEMMs into one.
    const float* Wv = in_w + (long)2 * DDIM * DDIM;
    const float* bv = in_b + 2 * DDIM;

    // --- all prep in ONE launch ---
    prep_all<<<41984, 256>>>(x, out_w, Wv, bv, out_b, W1, W2, W3,
                             xb, wob, wvt, w1b, w2b, w3b, bc);

    // Wc = Wo @ Wv  (bf16 out)
    gemm_bf16<0, 1><<<dim3(8, 8, 1), 256, SMEM_SZ>>>(
        wob, wvt, zeros, wcb, DDIM, DDIM, 0, 0, 0, 0);

    // a = x @ Wc^T + bc  (bf16 out)
    gemm_bf16<0, 1><<<dim3(8, 64, 1), 256, SMEM_SZ>>>(
        xb, wcb, bc, ab, DDIM, DDIM, 0, 0, 0, 0);

    // h1[m] = a @ W1[m] + b1[m]  (bf16 out)
    gemm_bf16<0, 1><<<dim3(8, 64, MMASK), 256, SMEM_SZ>>>(
        ab, w1b, b1, h1b, HDIM, DDIM,
        0, (long)HDIM * DDIM, (long)HDIM, (long)BSZ * HDIM);

    // LayerNorm + GELU in place (bf16)
    ln_gelu_bf<<<MMASK * BSZ, 128>>>(h1b, ln_g, ln_b);

    // h2[m] = gelu( h1[m] @ W2[m] + b2[m] )  (bf16 out)
    gemm_bf16<1, 1><<<dim3(4, 64, MMASK), 256, SMEM_SZ>>>(
        h1b, w2b, b2, h2b, H2DIM, HDIM,
        (long)BSZ * HDIM, (long)H2DIM * HDIM, (long)H2DIM, (long)BSZ * H2DIM);

    // out[m] = sigmoid( h2[m] @ W3[m] + b3[m] )  (f32 out)
    gemm_bf16<2, 0><<<dim3(8, 64, MMASK), 256, SMEM_SZ>>>(
        h2b, w3b, b3, out, DDIM, H2DIM,
        (long)BSZ * H2DIM, (long)DDIM * H2DIM, (long)DDIM, (long)BSZ * DDIM);
}